// round 12
// baseline (speedup 1.0000x reference)
#include <cuda_runtime.h>
#include <cuda_bf16.h>
#include <math.h>
#include <stdint.h>

#define NN 8192
#define EE 262144
#define ETOT 270336   /* EE + NN self loops */
#define INF_ 512
#define HF 128
#define OF 64
#define KCL 16
#define NTILE 64      /* NN / 128 */
#define NPAIR 2080    /* NTILE*(NTILE+1)/2 */

// ---------------- scratch (device globals: no allocation allowed) ------------
__device__ float g_h1[NN * HF];     // x @ W1
__device__ float g_x2[NN * HF];     // elu(gat1)
__device__ float g_h2[NN * OF];     // x2 @ W2
__device__ float g_as1[NN], g_ad1[NN];
__device__ float g_as2[NN], g_ad2[NN];
__device__ int   g_cnt[NN];
__device__ int   g_fill[NN];
__device__ int   g_off[NN + 1];
__device__ int   g_srcs[ETOT];
__device__ __nv_bfloat16 g_zhi[NN * OF];
__device__ __nv_bfloat16 g_zlo[NN * OF];
__device__ __nv_bfloat16 g_w1thi[HF * INF_];   // W1^T
__device__ __nv_bfloat16 g_w1tlo[HF * INF_];

// ---- W1 [512,128] -> W1T hi/lo [128,512], coalesced via 32x33 smem tiles ----
__global__ __launch_bounds__(256) void cvt_w1t(const float* __restrict__ W1,
                                               __nv_bfloat16* __restrict__ wh,
                                               __nv_bfloat16* __restrict__ wl) {
    __shared__ float tile[32][33];
    const int tx = threadIdx.x & 31, ty = threadIdx.x >> 5;   // 32 x 8
    const int nb = blockIdx.x & 3, kb = blockIdx.x >> 2;      // 4 n-tiles x 16 k-tiles
    const int k0 = kb * 32, n0 = nb * 32;
#pragma unroll
    for (int i = 0; i < 4; i++) {
        int kr = ty + i * 8;
        tile[kr][tx] = W1[(size_t)(k0 + kr) * HF + n0 + tx];
    }
    __syncthreads();
#pragma unroll
    for (int i = 0; i < 4; i++) {
        int nr = ty + i * 8;
        float v = tile[tx][nr];
        __nv_bfloat16 h = __float2bfloat16(v);
        size_t o = (size_t)(n0 + nr) * INF_ + k0 + tx;
        wh[o] = h;
        wl[o] = __float2bfloat16(v - __bfloat162float(h));
    }
}

// ---------------- HMMA + LDSM helpers ----------------------------------------
__device__ __forceinline__ void mma_bf16(float c[4], const uint32_t a[4],
                                         const uint32_t b[2]) {
    asm volatile(
        "mma.sync.aligned.m16n8k16.row.col.f32.bf16.bf16.f32 "
        "{%0,%1,%2,%3}, {%4,%5,%6,%7}, {%8,%9}, {%0,%1,%2,%3};"
        : "+f"(c[0]), "+f"(c[1]), "+f"(c[2]), "+f"(c[3])
        : "r"(a[0]), "r"(a[1]), "r"(a[2]), "r"(a[3]), "r"(b[0]), "r"(b[1]));
}

#define LDSM4(r, addr) \
    asm volatile("ldmatrix.sync.aligned.m8n8.x4.shared.b16 {%0,%1,%2,%3}, [%4];" \
                 : "=r"((r)[0]), "=r"((r)[1]), "=r"((r)[2]), "=r"((r)[3]) \
                 : "r"(addr))

#define ROWB 144                    // padded smem row stride in bytes (72 bf16)

// ===== gemm1: h1 = x @ W1 (fused fp32->hi/lo conversion + fused alphas) ======
#define G1_AHI 0
#define G1_ALO (64 * ROWB)
#define G1_BHI (2 * 64 * ROWB)
#define G1_BLO (G1_BHI + 128 * ROWB)
#define G1_TOTAL (G1_BHI + 2 * 128 * ROWB)   // 55296 B
#define G1_ALO_OFF (64 * ROWB)
#define G1_BLO_OFF (128 * ROWB)

__global__ __launch_bounds__(256) void gemm1_fused(const float* __restrict__ x,
                                                   const __nv_bfloat16* __restrict__ wh,
                                                   const __nv_bfloat16* __restrict__ wl,
                                                   const float* __restrict__ a_src,
                                                   const float* __restrict__ a_dst,
                                                   float* __restrict__ h1,
                                                   float* __restrict__ os,
                                                   float* __restrict__ od) {
    extern __shared__ char sm[];
    const uint32_t smb = (uint32_t)__cvta_generic_to_shared(sm);
    __shared__ float red[2][2][64];   // [wn][s|d][local row]
    const int tid = threadIdx.x;
    const int bm = blockIdx.x * 64;
    const int wid = tid >> 5, lane = tid & 31;
    const int wm = wid & 3, wn = wid >> 2;
    const int g = lane >> 2, tg = lane & 3;
    const int sub = lane >> 3, lrow = lane & 7;

    float c[8][4] = {};

    const uint32_t aAddr = smb + G1_AHI +
        (uint32_t)(wm * 16 + (sub & 1) * 8 + lrow) * ROWB + (sub >> 1) * 16;
    const uint32_t bAddr = smb + G1_BHI +
        (uint32_t)(wn * 64 + (sub >> 1) * 8 + lrow) * ROWB + (sub & 1) * 16;

    for (int kc = 0; kc < 8; kc++) {
        const int k0 = kc * 64;
#pragma unroll
        for (int t = tid; t < 1024; t += 256) {
            int r = t >> 4, c4 = t & 15;
            float4 v = *(const float4*)&x[(size_t)(bm + r) * INF_ + k0 + c4 * 4];
            __nv_bfloat16 h0 = __float2bfloat16(v.x), h1v = __float2bfloat16(v.y);
            __nv_bfloat16 h2 = __float2bfloat16(v.z), h3 = __float2bfloat16(v.w);
            __nv_bfloat16 l0 = __float2bfloat16(v.x - __bfloat162float(h0));
            __nv_bfloat16 l1 = __float2bfloat16(v.y - __bfloat162float(h1v));
            __nv_bfloat16 l2 = __float2bfloat16(v.z - __bfloat162float(h2));
            __nv_bfloat16 l3 = __float2bfloat16(v.w - __bfloat162float(h3));
            char* pa = sm + G1_AHI + r * ROWB + c4 * 8;
            *(__nv_bfloat162*)(pa)     = __nv_bfloat162(h0, h1v);
            *(__nv_bfloat162*)(pa + 4) = __nv_bfloat162(h2, h3);
            char* pl = sm + G1_ALO + r * ROWB + c4 * 8;
            *(__nv_bfloat162*)(pl)     = __nv_bfloat162(l0, l1);
            *(__nv_bfloat162*)(pl + 4) = __nv_bfloat162(l2, l3);
        }
#pragma unroll
        for (int t = tid; t < 1024; t += 256) {
            int r = t >> 3, cc = t & 7;
            *(uint4*)(sm + G1_BHI + r * ROWB + cc * 16) =
                *(const uint4*)(wh + (size_t)r * INF_ + k0 + cc * 8);
            *(uint4*)(sm + G1_BLO + r * ROWB + cc * 16) =
                *(const uint4*)(wl + (size_t)r * INF_ + k0 + cc * 8);
        }
        __syncthreads();

#pragma unroll
        for (int k = 0; k < 4; k++) {
            const int kb = k * 32;
            uint32_t ah[4], al[4];
            LDSM4(ah, aAddr + kb);
            LDSM4(al, aAddr + G1_ALO_OFF + kb);
#pragma unroll
            for (int pp = 0; pp < 4; pp++) {
                uint32_t bh[4], bl[4];
                LDSM4(bh, bAddr + pp * (16 * ROWB) + kb);
                LDSM4(bl, bAddr + pp * (16 * ROWB) + G1_BLO_OFF + kb);
                const int n0 = 2 * pp, n1 = 2 * pp + 1;
                mma_bf16(c[n0], ah, &bh[0]);
                mma_bf16(c[n1], ah, &bh[2]);
                mma_bf16(c[n0], ah, &bl[0]);
                mma_bf16(c[n1], ah, &bl[2]);
                mma_bf16(c[n0], al, &bh[0]);
                mma_bf16(c[n1], al, &bh[2]);
            }
        }
        __syncthreads();
    }

    const int r0 = bm + wm * 16 + g;
    const int col0 = wn * 64 + tg * 2;
    float ssA = 0.f, sdA = 0.f, ssB = 0.f, sdB = 0.f;
#pragma unroll
    for (int nt = 0; nt < 8; nt++) {
        *(float2*)&h1[(size_t)r0 * HF + col0 + nt * 8]       = make_float2(c[nt][0], c[nt][1]);
        *(float2*)&h1[(size_t)(r0 + 8) * HF + col0 + nt * 8] = make_float2(c[nt][2], c[nt][3]);
        float a0 = __ldg(&a_src[col0 + nt * 8]), a1 = __ldg(&a_src[col0 + nt * 8 + 1]);
        float d0 = __ldg(&a_dst[col0 + nt * 8]), d1 = __ldg(&a_dst[col0 + nt * 8 + 1]);
        ssA += c[nt][0] * a0 + c[nt][1] * a1;
        sdA += c[nt][0] * d0 + c[nt][1] * d1;
        ssB += c[nt][2] * a0 + c[nt][3] * a1;
        sdB += c[nt][2] * d0 + c[nt][3] * d1;
    }
#pragma unroll
    for (int o = 1; o <= 2; o <<= 1) {
        ssA += __shfl_xor_sync(0xffffffffu, ssA, o);
        sdA += __shfl_xor_sync(0xffffffffu, sdA, o);
        ssB += __shfl_xor_sync(0xffffffffu, ssB, o);
        sdB += __shfl_xor_sync(0xffffffffu, sdB, o);
    }
    const int rowA = wm * 16 + g, rowB = rowA + 8;
    if (tg == 0) {
        red[wn][0][rowA] = ssA; red[wn][0][rowB] = ssB;
        red[wn][1][rowA] = sdA; red[wn][1][rowB] = sdB;
    }
    __syncthreads();
    if (tid < 64) {
        os[bm + tid] = red[0][0][tid] + red[1][0][tid];
        od[bm + tid] = red[0][1][tid] + red[1][1][tid];
    }
}

// ============ A_pred = sigmoid(z z^T): ldmatrix + fused hi/lo mainloop =======
#define TILE_B (128 * ROWB)
#define ZT_AHI 0
#define ZT_ALO TILE_B
#define ZT_BHI (2 * TILE_B)
#define ZT_BLO (3 * TILE_B)
#define ZT_TOTAL (4 * TILE_B)       // 73728 B; mirror stage reuses it

__global__ __launch_bounds__(256, 2) void zzt_sym(const __nv_bfloat16* __restrict__ zh,
                                                  const __nv_bfloat16* __restrict__ zl,
                                                  float* __restrict__ out) {
    extern __shared__ char sm[];
    const uint32_t smb = (uint32_t)__cvta_generic_to_shared(sm);
    const int tid = threadIdx.x;

    int p = blockIdx.x;
    int bi = (int)((2.0f * NTILE + 1.0f -
                    sqrtf((2.0f * NTILE + 1.0f) * (2.0f * NTILE + 1.0f) - 8.0f * p)) * 0.5f);
    if (bi < 0) bi = 0;
    if (bi > NTILE - 1) bi = NTILE - 1;
    while (bi > 0 && bi * NTILE - bi * (bi - 1) / 2 > p) bi--;
    while ((bi + 1) * NTILE - (bi + 1) * bi / 2 <= p) bi++;
    const int bj = bi + (p - (bi * NTILE - bi * (bi - 1) / 2));
    const int bm = bi * 128, bn = bj * 128;

#pragma unroll
    for (int t = tid; t < 1024; t += 256) {
        int r = t >> 3, c = t & 7;
        *(uint4*)(sm + ZT_AHI + r * ROWB + c * 16) = *(const uint4*)(zh + (size_t)(bm + r) * 64 + c * 8);
        *(uint4*)(sm + ZT_ALO + r * ROWB + c * 16) = *(const uint4*)(zl + (size_t)(bm + r) * 64 + c * 8);
        *(uint4*)(sm + ZT_BHI + r * ROWB + c * 16) = *(const uint4*)(zh + (size_t)(bn + r) * 64 + c * 8);
        *(uint4*)(sm + ZT_BLO + r * ROWB + c * 16) = *(const uint4*)(zl + (size_t)(bn + r) * 64 + c * 8);
    }
    __syncthreads();

    const int wid = tid >> 5, lane = tid & 31;
    const int wm = wid & 3, wn = wid >> 2;
    const int sub = lane >> 3, lrow = lane & 7;

    const uint32_t aAddr0 = smb + ZT_AHI +
        (uint32_t)(wm * 32 + (sub & 1) * 8 + lrow) * ROWB + (sub >> 1) * 16;
    const uint32_t aAddr1 = aAddr0 + 16 * ROWB;
    const uint32_t bAddr = smb + ZT_BHI +
        (uint32_t)(wn * 64 + (sub >> 1) * 8 + lrow) * ROWB + (sub & 1) * 16;

    float c[2][8][4] = {};

#pragma unroll
    for (int k = 0; k < 4; k++) {
        const int kb = k * 32;
        uint32_t ah[2][4], al[2][4];
        LDSM4(ah[0], aAddr0 + kb);
        LDSM4(ah[1], aAddr1 + kb);
        LDSM4(al[0], aAddr0 + TILE_B + kb);
        LDSM4(al[1], aAddr1 + TILE_B + kb);
#pragma unroll
        for (int pp = 0; pp < 4; pp++) {
            uint32_t bh[4], bl[4];
            LDSM4(bh, bAddr + pp * (16 * ROWB) + kb);
            LDSM4(bl, bAddr + pp * (16 * ROWB) + TILE_B + kb);
            const int n0 = 2 * pp, n1 = 2 * pp + 1;
#pragma unroll
            for (int mt = 0; mt < 2; mt++) {
                mma_bf16(c[mt][n0], ah[mt], &bh[0]);
                mma_bf16(c[mt][n1], ah[mt], &bh[2]);
                mma_bf16(c[mt][n0], ah[mt], &bl[0]);
                mma_bf16(c[mt][n1], ah[mt], &bl[2]);
                mma_bf16(c[mt][n0], al[mt], &bh[0]);
                mma_bf16(c[mt][n1], al[mt], &bh[2]);
            }
        }
    }

    __syncthreads();
    float (*S)[129] = (float(*)[129])sm;
    const bool mirror = (bi != bj);
    const int g = lane >> 2, tg = lane & 3;

#pragma unroll
    for (int mt = 0; mt < 2; mt++) {
        const int r0 = wm * 32 + mt * 16 + g;
        const int c0 = wn * 64 + tg * 2;
#pragma unroll
        for (int nt = 0; nt < 8; nt++) {
            float s0 = 1.0f / (1.0f + __expf(-c[mt][nt][0]));
            float s1 = 1.0f / (1.0f + __expf(-c[mt][nt][1]));
            float s2 = 1.0f / (1.0f + __expf(-c[mt][nt][2]));
            float s3 = 1.0f / (1.0f + __expf(-c[mt][nt][3]));
            *(float2*)&out[(size_t)(bm + r0) * NN + bn + c0 + nt * 8]     = make_float2(s0, s1);
            *(float2*)&out[(size_t)(bm + r0 + 8) * NN + bn + c0 + nt * 8] = make_float2(s2, s3);
            if (mirror) {
                S[r0][c0 + nt * 8]         = s0;
                S[r0][c0 + nt * 8 + 1]     = s1;
                S[r0 + 8][c0 + nt * 8]     = s2;
                S[r0 + 8][c0 + nt * 8 + 1] = s3;
            }
        }
    }
    if (mirror) {
        __syncthreads();
#pragma unroll 4
        for (int v = 0; v < 16; v++) {
            int idx = v * 256 + tid;
            int rr = idx >> 5, qc = (idx & 31) * 4;
            float4 o;
            o.x = S[qc + 0][rr];
            o.y = S[qc + 1][rr];
            o.z = S[qc + 2][rr];
            o.w = S[qc + 3][rr];
            *(float4*)&out[(size_t)(bn + rr) * NN + bm + qc] = o;
        }
    }
}

// ------ layer-2 GEMM (fp32 SIMT, 64x64 tiles) with fused alpha dots ----------
__global__ __launch_bounds__(256) void gemm2_a(const float* __restrict__ A,
                                               const float* __restrict__ B,
                                               const float* __restrict__ a_src,
                                               const float* __restrict__ a_dst,
                                               float* __restrict__ C,
                                               float* __restrict__ os,
                                               float* __restrict__ od) {
    __shared__ float As[16][64];
    __shared__ float Bs[16][64];
    const int tid = threadIdx.x;
    const int bm = blockIdx.x * 64;
    const int ty = tid >> 4, tx = tid & 15;
    float acc[4][4] = {};
    const int ra = tid >> 2, ka = (tid & 3) * 4;
    const int kb = tid >> 4, nb = (tid & 15) * 4;
    for (int k0 = 0; k0 < HF; k0 += 16) {
        float4 av = *(const float4*)&A[(size_t)(bm + ra) * HF + k0 + ka];
        float4 bv = *(const float4*)&B[(size_t)(k0 + kb) * OF + nb];
        As[ka + 0][ra] = av.x; As[ka + 1][ra] = av.y;
        As[ka + 2][ra] = av.z; As[ka + 3][ra] = av.w;
        *(float4*)&Bs[kb][nb] = bv;
        __syncthreads();
#pragma unroll
        for (int k = 0; k < 16; k++) {
            float4 a4 = *(const float4*)&As[k][ty * 4];
            float4 b4 = *(const float4*)&Bs[k][tx * 4];
            acc[0][0] += a4.x * b4.x; acc[0][1] += a4.x * b4.y;
            acc[0][2] += a4.x * b4.z; acc[0][3] += a4.x * b4.w;
            acc[1][0] += a4.y * b4.x; acc[1][1] += a4.y * b4.y;
            acc[1][2] += a4.y * b4.z; acc[1][3] += a4.y * b4.w;
            acc[2][0] += a4.z * b4.x; acc[2][1] += a4.z * b4.y;
            acc[2][2] += a4.z * b4.z; acc[2][3] += a4.z * b4.w;
            acc[3][0] += a4.w * b4.x; acc[3][1] += a4.w * b4.y;
            acc[3][2] += a4.w * b4.z; acc[3][3] += a4.w * b4.w;
        }
        __syncthreads();
    }
    float ss[4], sd[4];
#pragma unroll
    for (int i = 0; i < 4; i++) {
        float4 o = make_float4(acc[i][0], acc[i][1], acc[i][2], acc[i][3]);
        *(float4*)&C[(size_t)(bm + ty * 4 + i) * OF + tx * 4] = o;
        float a0 = __ldg(&a_src[tx * 4]),     d0 = __ldg(&a_dst[tx * 4]);
        float a1 = __ldg(&a_src[tx * 4 + 1]), d1 = __ldg(&a_dst[tx * 4 + 1]);
        float a2 = __ldg(&a_src[tx * 4 + 2]), d2 = __ldg(&a_dst[tx * 4 + 2]);
        float a3 = __ldg(&a_src[tx * 4 + 3]), d3 = __ldg(&a_dst[tx * 4 + 3]);
        ss[i] = acc[i][0] * a0 + acc[i][1] * a1 + acc[i][2] * a2 + acc[i][3] * a3;
        sd[i] = acc[i][0] * d0 + acc[i][1] * d1 + acc[i][2] * d2 + acc[i][3] * d3;
    }
#pragma unroll
    for (int o = 1; o <= 8; o <<= 1) {
#pragma unroll
        for (int i = 0; i < 4; i++) {
            ss[i] += __shfl_xor_sync(0xffffffffu, ss[i], o);
            sd[i] += __shfl_xor_sync(0xffffffffu, sd[i], o);
        }
    }
    if (tx == 0) {
#pragma unroll
        for (int i = 0; i < 4; i++) {
            os[bm + ty * 4 + i] = ss[i];
            od[bm + ty * 4 + i] = sd[i];
        }
    }
}

// ---------------- CSR build (1 edge/thread; self loops folded in scan) --------
__global__ void count_edges(const int* __restrict__ ei) {
    int i = blockIdx.x * blockDim.x + threadIdx.x;
    atomicAdd(&g_cnt[ei[EE + i]], 1);
}

__global__ __launch_bounds__(1024) void scan_kernel() {
    __shared__ int sh[1024];
    int tid = threadIdx.x;
    int local[8];
    int s = 0;
#pragma unroll
    for (int j = 0; j < 8; j++) { local[j] = g_cnt[tid * 8 + j] + 1; s += local[j]; }
    sh[tid] = s;
    __syncthreads();
    for (int off = 1; off < 1024; off <<= 1) {
        int v = (tid >= off) ? sh[tid - off] : 0;
        __syncthreads();
        sh[tid] += v;
        __syncthreads();
    }
    int run = sh[tid] - s;  // exclusive prefix
#pragma unroll
    for (int j = 0; j < 8; j++) {
        int node = tid * 8 + j;
        g_off[node] = run;
        g_srcs[run] = node;   // self loop goes first
        g_fill[node] = 1;
        run += local[j];
    }
    if (tid == 1023) g_off[NN] = run;
}

__global__ void scatter_edges(const int* __restrict__ ei) {
    int i = blockIdx.x * blockDim.x + threadIdx.x;
    int src = ei[i], dst = ei[EE + i];
    int pos = g_off[dst] + atomicAdd(&g_fill[dst], 1);
    g_srcs[pos] = src;
}

// ------ GAT softmax-aggregate: warp-synchronous, L=F/4 lanes per dst ---------
// Each lane owns 4 features and accumulates acc4 and the full weight sum s.
// Softmax weights broadcast via shfl; no smem, no __syncthreads.
template <int F, bool DO_ELU, bool EMIT_HILO>
__global__ __launch_bounds__(256) void gat_aggregate(const float* __restrict__ h,
                                                     const float* __restrict__ as,
                                                     const float* __restrict__ adv,
                                                     const float* __restrict__ bias,
                                                     float* __restrict__ out,
                                                     __nv_bfloat16* __restrict__ zh,
                                                     __nv_bfloat16* __restrict__ zl) {
    constexpr int L = F / 4;          // lanes per dst: 32 (F=128) or 16 (F=64)
    constexpr int DPB = 256 / L;      // dsts per block
    const int tid = threadIdx.x;
    const int dst = blockIdx.x * DPB + tid / L;
    const int lane = tid % L;
    const int beg = g_off[dst], end = g_off[dst + 1];
    const float ad = adv[dst];

    float4 acc = make_float4(0.f, 0.f, 0.f, 0.f);
    float s = 0.f;

    for (int j0 = beg; j0 < end; j0 += L) {
        int j = j0 + lane;
        float w = 0.f;
        int sidx = 0;
        if (j < end) {
            sidx = g_srcs[j];
            float e = as[sidx] + ad;
            e = e > 0.f ? e : 0.2f * e;
            w = __expf(e);
        }
        const int cnt = min(L, end - j0);
#pragma unroll 4
        for (int c = 0; c < cnt; c++) {
            float wc = __shfl_sync(0xffffffffu, w, c, L);
            int   sc = __shfl_sync(0xffffffffu, sidx, c, L);
            float4 hv = *(const float4*)&h[(size_t)sc * F + lane * 4];
            s += wc;
            acc.x += wc * hv.x; acc.y += wc * hv.y;
            acc.z += wc * hv.z; acc.w += wc * hv.w;
        }
    }

    const float inv = __fdividef(1.0f, s);
    float4 bi = *(const float4*)&bias[lane * 4];
    float4 v;
    v.x = acc.x * inv + bi.x;
    v.y = acc.y * inv + bi.y;
    v.z = acc.z * inv + bi.z;
    v.w = acc.w * inv + bi.w;
    if (DO_ELU) {
        v.x = v.x > 0.f ? v.x : (__expf(v.x) - 1.0f);
        v.y = v.y > 0.f ? v.y : (__expf(v.y) - 1.0f);
        v.z = v.z > 0.f ? v.z : (__expf(v.z) - 1.0f);
        v.w = v.w > 0.f ? v.w : (__expf(v.w) - 1.0f);
    }
    *(float4*)&out[(size_t)dst * F + lane * 4] = v;
    if (EMIT_HILO) {
        __nv_bfloat16 h0 = __float2bfloat16(v.x), h1 = __float2bfloat16(v.y);
        __nv_bfloat16 h2 = __float2bfloat16(v.z), h3 = __float2bfloat16(v.w);
        __nv_bfloat16 l0 = __float2bfloat16(v.x - __bfloat162float(h0));
        __nv_bfloat16 l1 = __float2bfloat16(v.y - __bfloat162float(h1));
        __nv_bfloat16 l2 = __float2bfloat16(v.z - __bfloat162float(h2));
        __nv_bfloat16 l3 = __float2bfloat16(v.w - __bfloat162float(h3));
        *(__nv_bfloat162*)&zh[(size_t)dst * F + lane * 4]     = __nv_bfloat162(h0, h1);
        *(__nv_bfloat162*)&zh[(size_t)dst * F + lane * 4 + 2] = __nv_bfloat162(h2, h3);
        *(__nv_bfloat162*)&zl[(size_t)dst * F + lane * 4]     = __nv_bfloat162(l0, l1);
        *(__nv_bfloat162*)&zl[(size_t)dst * F + lane * 4 + 2] = __nv_bfloat162(l2, l3);
    }
}

// ---------------- student-t soft assignment q ---------------------------------
__global__ __launch_bounds__(128) void q_kernel(const float* __restrict__ z,
                                                const float* __restrict__ centers,
                                                float* __restrict__ q) {
    __shared__ float c[KCL * OF];
    for (int i = threadIdx.x; i < KCL * OF; i += blockDim.x) c[i] = centers[i];
    __syncthreads();
    int node = blockIdx.x * blockDim.x + threadIdx.x;
    if (node >= NN) return;
    float zr[OF];
#pragma unroll
    for (int f = 0; f < OF; f++) zr[f] = z[(size_t)node * OF + f];
    float qs[KCL];
    float tot = 0.f;
#pragma unroll
    for (int k = 0; k < KCL; k++) {
        float d2 = 0.f;
#pragma unroll
        for (int f = 0; f < OF; f++) {
            float d = zr[f] - c[k * OF + f];
            d2 += d * d;
        }
        float qk = 1.0f / (1.0f + d2);
        qs[k] = qk;
        tot += qk;
    }
    float inv = 1.0f / tot;
#pragma unroll
    for (int k = 0; k < KCL; k++) q[(size_t)node * KCL + k] = qs[k] * inv;
}

// ---------------- launcher ----------------------------------------------------
extern "C" void kernel_launch(void* const* d_in, const int* in_sizes, int n_in,
                              void* d_out, int out_size) {
    const float* x      = (const float*)d_in[0];
    const int*   ei     = (const int*)d_in[1];
    const float* W1     = (const float*)d_in[2];
    const float* a_src1 = (const float*)d_in[3];
    const float* a_dst1 = (const float*)d_in[4];
    const float* b1     = (const float*)d_in[5];
    const float* W2     = (const float*)d_in[6];
    const float* a_src2 = (const float*)d_in[7];
    const float* a_dst2 = (const float*)d_in[8];
    const float* b2     = (const float*)d_in[9];
    const float* centers= (const float*)d_in[10];

    float* out    = (float*)d_out;
    float* z_out  = out;                         // [NN, OF]
    float* apred  = out + (size_t)NN * OF;       // [NN, NN]
    float* q_out  = apred + (size_t)NN * NN;     // [NN, KCL]

    float *h1, *x2, *h2, *as1, *ad1, *as2, *ad2;
    int *cnt;
    __nv_bfloat16 *zh, *zl, *wh, *wl;
    cudaGetSymbolAddress((void**)&h1,  g_h1);
    cudaGetSymbolAddress((void**)&x2,  g_x2);
    cudaGetSymbolAddress((void**)&h2,  g_h2);
    cudaGetSymbolAddress((void**)&as1, g_as1);
    cudaGetSymbolAddress((void**)&ad1, g_ad1);
    cudaGetSymbolAddress((void**)&as2, g_as2);
    cudaGetSymbolAddress((void**)&ad2, g_ad2);
    cudaGetSymbolAddress((void**)&zh,  g_zhi);
    cudaGetSymbolAddress((void**)&zl,  g_zlo);
    cudaGetSymbolAddress((void**)&wh,  g_w1thi);
    cudaGetSymbolAddress((void**)&wl,  g_w1tlo);
    cudaGetSymbolAddress((void**)&cnt, g_cnt);

    cudaFuncSetAttribute(zzt_sym, cudaFuncAttributeMaxDynamicSharedMemorySize, ZT_TOTAL);
    cudaFuncSetAttribute(gemm1_fused, cudaFuncAttributeMaxDynamicSharedMemorySize, G1_TOTAL);

    static cudaStream_t s_side = nullptr;
    static cudaEvent_t ev_fork = nullptr, ev_csr = nullptr, ev_z = nullptr, ev_q = nullptr;
    if (s_side == nullptr) {
        cudaStreamCreateWithFlags(&s_side, cudaStreamNonBlocking);
        cudaEventCreateWithFlags(&ev_fork, cudaEventDisableTiming);
        cudaEventCreateWithFlags(&ev_csr,  cudaEventDisableTiming);
        cudaEventCreateWithFlags(&ev_z,    cudaEventDisableTiming);
        cudaEventCreateWithFlags(&ev_q,    cudaEventDisableTiming);
    }

    if (s_side != nullptr) {
        // ---- fork: CSR build on side stream, gemm1 path on main ----
        cudaEventRecord(ev_fork, 0);
        cudaStreamWaitEvent(s_side, ev_fork, 0);
        cudaMemsetAsync(cnt, 0, NN * sizeof(int), s_side);
        count_edges<<<EE / 256, 256, 0, s_side>>>(ei);
        scan_kernel<<<1, 1024, 0, s_side>>>();
        scatter_edges<<<EE / 256, 256, 0, s_side>>>(ei);
        cudaEventRecord(ev_csr, s_side);

        cvt_w1t<<<64, 256>>>(W1, wh, wl);
        gemm1_fused<<<NN / 64, 256, G1_TOTAL>>>(x, wh, wl, a_src1, a_dst1, h1, as1, ad1);

        // ---- join: aggregate needs CSR + gemm1 ----
        cudaStreamWaitEvent(0, ev_csr, 0);
        gat_aggregate<HF, true, false><<<NN / 8, 256>>>(h1, as1, ad1, b1, x2, nullptr, nullptr);

        gemm2_a<<<NN / 64, 256>>>(x2, W2, a_src2, a_dst2, h2, as2, ad2);
        gat_aggregate<OF, false, true><<<NN / 16, 256>>>(h2, as2, ad2, b2, z_out, zh, zl);

        // ---- fork: q on side (needs z), zzt on main (needs zh/zl) ----
        cudaEventRecord(ev_z, 0);
        cudaStreamWaitEvent(s_side, ev_z, 0);
        q_kernel<<<NN / 128, 128, 0, s_side>>>(z_out, centers, q_out);
        cudaEventRecord(ev_q, s_side);

        zzt_sym<<<NPAIR, 256, ZT_TOTAL>>>(zh, zl, apred);
        cudaStreamWaitEvent(0, ev_q, 0);
    } else {
        // fallback: sequential on default stream
        cudaMemsetAsync(cnt, 0, NN * sizeof(int));
        count_edges<<<EE / 256, 256>>>(ei);
        scan_kernel<<<1, 1024>>>();
        scatter_edges<<<EE / 256, 256>>>(ei);
        cvt_w1t<<<64, 256>>>(W1, wh, wl);
        gemm1_fused<<<NN / 64, 256, G1_TOTAL>>>(x, wh, wl, a_src1, a_dst1, h1, as1, ad1);
        gat_aggregate<HF, true, false><<<NN / 8, 256>>>(h1, as1, ad1, b1, x2, nullptr, nullptr);
        gemm2_a<<<NN / 64, 256>>>(x2, W2, a_src2, a_dst2, h2, as2, ad2);
        gat_aggregate<OF, false, true><<<NN / 16, 256>>>(h2, as2, ad2, b2, z_out, zh, zl);
        zzt_sym<<<NPAIR, 256, ZT_TOTAL>>>(zh, zl, apred);
        q_kernel<<<NN / 128, 128>>>(z_out, centers, q_out);
    }
}

// round 14
// speedup vs baseline: 1.0123x; 1.0123x over previous
#include <cuda_runtime.h>
#include <cuda_bf16.h>
#include <math.h>
#include <stdint.h>

#define NN 8192
#define EE 262144
#define ETOT 270336   /* EE + NN self loops */
#define INF_ 512
#define HF 128
#define OF 64
#define KCL 16
#define NTILE 64      /* NN / 128 */
#define NPAIR 2080    /* NTILE*(NTILE+1)/2 */

// ---------------- scratch (device globals: no allocation allowed) ------------
__device__ float g_h1[NN * HF];     // x @ W1
__device__ float g_x2[NN * HF];     // elu(gat1)
__device__ float g_h2[NN * OF];     // x2 @ W2
__device__ float g_as1[NN], g_ad1[NN];
__device__ float g_as2[NN], g_ad2[NN];
__device__ int   g_cnt[NN];
__device__ int   g_fill[NN];
__device__ int   g_off[NN + 1];
__device__ int   g_srcs[ETOT];
__device__ __nv_bfloat16 g_zhi[NN * OF];
__device__ __nv_bfloat16 g_zlo[NN * OF];
__device__ __nv_bfloat16 g_w1thi[HF * INF_];   // W1^T
__device__ __nv_bfloat16 g_w1tlo[HF * INF_];

// ---- W1 [512,128] -> W1T hi/lo [128,512], coalesced via 32x33 smem tiles ----
__global__ __launch_bounds__(256) void cvt_w1t(const float* __restrict__ W1,
                                               __nv_bfloat16* __restrict__ wh,
                                               __nv_bfloat16* __restrict__ wl) {
    __shared__ float tile[32][33];
    const int tx = threadIdx.x & 31, ty = threadIdx.x >> 5;   // 32 x 8
    const int nb = blockIdx.x & 3, kb = blockIdx.x >> 2;      // 4 n-tiles x 16 k-tiles
    const int k0 = kb * 32, n0 = nb * 32;
#pragma unroll
    for (int i = 0; i < 4; i++) {
        int kr = ty + i * 8;
        tile[kr][tx] = W1[(size_t)(k0 + kr) * HF + n0 + tx];
    }
    __syncthreads();
#pragma unroll
    for (int i = 0; i < 4; i++) {
        int nr = ty + i * 8;
        float v = tile[tx][nr];
        __nv_bfloat16 h = __float2bfloat16(v);
        size_t o = (size_t)(n0 + nr) * INF_ + k0 + tx;
        wh[o] = h;
        wl[o] = __float2bfloat16(v - __bfloat162float(h));
    }
}

// ---------------- HMMA + LDSM helpers ----------------------------------------
__device__ __forceinline__ void mma_bf16(float c[4], const uint32_t a[4],
                                         const uint32_t b[2]) {
    asm volatile(
        "mma.sync.aligned.m16n8k16.row.col.f32.bf16.bf16.f32 "
        "{%0,%1,%2,%3}, {%4,%5,%6,%7}, {%8,%9}, {%0,%1,%2,%3};"
        : "+f"(c[0]), "+f"(c[1]), "+f"(c[2]), "+f"(c[3])
        : "r"(a[0]), "r"(a[1]), "r"(a[2]), "r"(a[3]), "r"(b[0]), "r"(b[1]));
}

#define LDSM4(r, addr) \
    asm volatile("ldmatrix.sync.aligned.m8n8.x4.shared.b16 {%0,%1,%2,%3}, [%4];" \
                 : "=r"((r)[0]), "=r"((r)[1]), "=r"((r)[2]), "=r"((r)[3]) \
                 : "r"(addr))

#define ROWB 144                    // padded smem row stride in bytes (72 bf16)

// ===== gemm1: h1 = x @ W1 (fused fp32->hi/lo conversion + fused alphas) ======
#define G1_AHI 0
#define G1_ALO (64 * ROWB)
#define G1_BHI (2 * 64 * ROWB)
#define G1_BLO (G1_BHI + 128 * ROWB)
#define G1_TOTAL (G1_BHI + 2 * 128 * ROWB)   // 55296 B
#define G1_ALO_OFF (64 * ROWB)
#define G1_BLO_OFF (128 * ROWB)

__global__ __launch_bounds__(256) void gemm1_fused(const float* __restrict__ x,
                                                   const __nv_bfloat16* __restrict__ wh,
                                                   const __nv_bfloat16* __restrict__ wl,
                                                   const float* __restrict__ a_src,
                                                   const float* __restrict__ a_dst,
                                                   float* __restrict__ h1,
                                                   float* __restrict__ os,
                                                   float* __restrict__ od) {
    extern __shared__ char sm[];
    const uint32_t smb = (uint32_t)__cvta_generic_to_shared(sm);
    __shared__ float red[2][2][64];   // [wn][s|d][local row]
    const int tid = threadIdx.x;
    const int bm = blockIdx.x * 64;
    const int wid = tid >> 5, lane = tid & 31;
    const int wm = wid & 3, wn = wid >> 2;
    const int g = lane >> 2, tg = lane & 3;
    const int sub = lane >> 3, lrow = lane & 7;

    float c[8][4] = {};

    const uint32_t aAddr = smb + G1_AHI +
        (uint32_t)(wm * 16 + (sub & 1) * 8 + lrow) * ROWB + (sub >> 1) * 16;
    const uint32_t bAddr = smb + G1_BHI +
        (uint32_t)(wn * 64 + (sub >> 1) * 8 + lrow) * ROWB + (sub & 1) * 16;

    for (int kc = 0; kc < 8; kc++) {
        const int k0 = kc * 64;
#pragma unroll
        for (int t = tid; t < 1024; t += 256) {
            int r = t >> 4, c4 = t & 15;
            float4 v = *(const float4*)&x[(size_t)(bm + r) * INF_ + k0 + c4 * 4];
            __nv_bfloat16 h0 = __float2bfloat16(v.x), h1v = __float2bfloat16(v.y);
            __nv_bfloat16 h2 = __float2bfloat16(v.z), h3 = __float2bfloat16(v.w);
            __nv_bfloat16 l0 = __float2bfloat16(v.x - __bfloat162float(h0));
            __nv_bfloat16 l1 = __float2bfloat16(v.y - __bfloat162float(h1v));
            __nv_bfloat16 l2 = __float2bfloat16(v.z - __bfloat162float(h2));
            __nv_bfloat16 l3 = __float2bfloat16(v.w - __bfloat162float(h3));
            char* pa = sm + G1_AHI + r * ROWB + c4 * 8;
            *(__nv_bfloat162*)(pa)     = __nv_bfloat162(h0, h1v);
            *(__nv_bfloat162*)(pa + 4) = __nv_bfloat162(h2, h3);
            char* pl = sm + G1_ALO + r * ROWB + c4 * 8;
            *(__nv_bfloat162*)(pl)     = __nv_bfloat162(l0, l1);
            *(__nv_bfloat162*)(pl + 4) = __nv_bfloat162(l2, l3);
        }
#pragma unroll
        for (int t = tid; t < 1024; t += 256) {
            int r = t >> 3, cc = t & 7;
            *(uint4*)(sm + G1_BHI + r * ROWB + cc * 16) =
                *(const uint4*)(wh + (size_t)r * INF_ + k0 + cc * 8);
            *(uint4*)(sm + G1_BLO + r * ROWB + cc * 16) =
                *(const uint4*)(wl + (size_t)r * INF_ + k0 + cc * 8);
        }
        __syncthreads();

#pragma unroll
        for (int k = 0; k < 4; k++) {
            const int kb = k * 32;
            uint32_t ah[4], al[4];
            LDSM4(ah, aAddr + kb);
            LDSM4(al, aAddr + G1_ALO_OFF + kb);
#pragma unroll
            for (int pp = 0; pp < 4; pp++) {
                uint32_t bh[4], bl[4];
                LDSM4(bh, bAddr + pp * (16 * ROWB) + kb);
                LDSM4(bl, bAddr + pp * (16 * ROWB) + G1_BLO_OFF + kb);
                const int n0 = 2 * pp, n1 = 2 * pp + 1;
                mma_bf16(c[n0], ah, &bh[0]);
                mma_bf16(c[n1], ah, &bh[2]);
                mma_bf16(c[n0], ah, &bl[0]);
                mma_bf16(c[n1], ah, &bl[2]);
                mma_bf16(c[n0], al, &bh[0]);
                mma_bf16(c[n1], al, &bh[2]);
            }
        }
        __syncthreads();
    }

    const int r0 = bm + wm * 16 + g;
    const int col0 = wn * 64 + tg * 2;
    float ssA = 0.f, sdA = 0.f, ssB = 0.f, sdB = 0.f;
#pragma unroll
    for (int nt = 0; nt < 8; nt++) {
        *(float2*)&h1[(size_t)r0 * HF + col0 + nt * 8]       = make_float2(c[nt][0], c[nt][1]);
        *(float2*)&h1[(size_t)(r0 + 8) * HF + col0 + nt * 8] = make_float2(c[nt][2], c[nt][3]);
        float a0 = __ldg(&a_src[col0 + nt * 8]), a1 = __ldg(&a_src[col0 + nt * 8 + 1]);
        float d0 = __ldg(&a_dst[col0 + nt * 8]), d1 = __ldg(&a_dst[col0 + nt * 8 + 1]);
        ssA += c[nt][0] * a0 + c[nt][1] * a1;
        sdA += c[nt][0] * d0 + c[nt][1] * d1;
        ssB += c[nt][2] * a0 + c[nt][3] * a1;
        sdB += c[nt][2] * d0 + c[nt][3] * d1;
    }
#pragma unroll
    for (int o = 1; o <= 2; o <<= 1) {
        ssA += __shfl_xor_sync(0xffffffffu, ssA, o);
        sdA += __shfl_xor_sync(0xffffffffu, sdA, o);
        ssB += __shfl_xor_sync(0xffffffffu, ssB, o);
        sdB += __shfl_xor_sync(0xffffffffu, sdB, o);
    }
    const int rowA = wm * 16 + g, rowB = rowA + 8;
    if (tg == 0) {
        red[wn][0][rowA] = ssA; red[wn][0][rowB] = ssB;
        red[wn][1][rowA] = sdA; red[wn][1][rowB] = sdB;
    }
    __syncthreads();
    if (tid < 64) {
        os[bm + tid] = red[0][0][tid] + red[1][0][tid];
        od[bm + tid] = red[0][1][tid] + red[1][1][tid];
    }
}

// ============ A_pred = sigmoid(z z^T): ldmatrix + fused hi/lo mainloop =======
#define TILE_B (128 * ROWB)
#define ZT_AHI 0
#define ZT_ALO TILE_B
#define ZT_BHI (2 * TILE_B)
#define ZT_BLO (3 * TILE_B)
#define ZT_TOTAL (4 * TILE_B)       // 73728 B; mirror stage reuses it

__global__ __launch_bounds__(256, 2) void zzt_sym(const __nv_bfloat16* __restrict__ zh,
                                                  const __nv_bfloat16* __restrict__ zl,
                                                  float* __restrict__ out) {
    extern __shared__ char sm[];
    const uint32_t smb = (uint32_t)__cvta_generic_to_shared(sm);
    const int tid = threadIdx.x;

    int p = blockIdx.x;
    int bi = (int)((2.0f * NTILE + 1.0f -
                    sqrtf((2.0f * NTILE + 1.0f) * (2.0f * NTILE + 1.0f) - 8.0f * p)) * 0.5f);
    if (bi < 0) bi = 0;
    if (bi > NTILE - 1) bi = NTILE - 1;
    while (bi > 0 && bi * NTILE - bi * (bi - 1) / 2 > p) bi--;
    while ((bi + 1) * NTILE - (bi + 1) * bi / 2 <= p) bi++;
    const int bj = bi + (p - (bi * NTILE - bi * (bi - 1) / 2));
    const int bm = bi * 128, bn = bj * 128;

#pragma unroll
    for (int t = tid; t < 1024; t += 256) {
        int r = t >> 3, c = t & 7;
        *(uint4*)(sm + ZT_AHI + r * ROWB + c * 16) = *(const uint4*)(zh + (size_t)(bm + r) * 64 + c * 8);
        *(uint4*)(sm + ZT_ALO + r * ROWB + c * 16) = *(const uint4*)(zl + (size_t)(bm + r) * 64 + c * 8);
        *(uint4*)(sm + ZT_BHI + r * ROWB + c * 16) = *(const uint4*)(zh + (size_t)(bn + r) * 64 + c * 8);
        *(uint4*)(sm + ZT_BLO + r * ROWB + c * 16) = *(const uint4*)(zl + (size_t)(bn + r) * 64 + c * 8);
    }
    __syncthreads();

    const int wid = tid >> 5, lane = tid & 31;
    const int wm = wid & 3, wn = wid >> 2;
    const int sub = lane >> 3, lrow = lane & 7;

    const uint32_t aAddr0 = smb + ZT_AHI +
        (uint32_t)(wm * 32 + (sub & 1) * 8 + lrow) * ROWB + (sub >> 1) * 16;
    const uint32_t aAddr1 = aAddr0 + 16 * ROWB;
    const uint32_t bAddr = smb + ZT_BHI +
        (uint32_t)(wn * 64 + (sub >> 1) * 8 + lrow) * ROWB + (sub & 1) * 16;

    float c[2][8][4] = {};

#pragma unroll
    for (int k = 0; k < 4; k++) {
        const int kb = k * 32;
        uint32_t ah[2][4], al[2][4];
        LDSM4(ah[0], aAddr0 + kb);
        LDSM4(ah[1], aAddr1 + kb);
        LDSM4(al[0], aAddr0 + TILE_B + kb);
        LDSM4(al[1], aAddr1 + TILE_B + kb);
#pragma unroll
        for (int pp = 0; pp < 4; pp++) {
            uint32_t bh[4], bl[4];
            LDSM4(bh, bAddr + pp * (16 * ROWB) + kb);
            LDSM4(bl, bAddr + pp * (16 * ROWB) + TILE_B + kb);
            const int n0 = 2 * pp, n1 = 2 * pp + 1;
#pragma unroll
            for (int mt = 0; mt < 2; mt++) {
                mma_bf16(c[mt][n0], ah[mt], &bh[0]);
                mma_bf16(c[mt][n1], ah[mt], &bh[2]);
                mma_bf16(c[mt][n0], ah[mt], &bl[0]);
                mma_bf16(c[mt][n1], ah[mt], &bl[2]);
                mma_bf16(c[mt][n0], al[mt], &bh[0]);
                mma_bf16(c[mt][n1], al[mt], &bh[2]);
            }
        }
    }

    __syncthreads();
    float (*S)[129] = (float(*)[129])sm;
    const bool mirror = (bi != bj);
    const int g = lane >> 2, tg = lane & 3;

#pragma unroll
    for (int mt = 0; mt < 2; mt++) {
        const int r0 = wm * 32 + mt * 16 + g;
        const int c0 = wn * 64 + tg * 2;
#pragma unroll
        for (int nt = 0; nt < 8; nt++) {
            float s0 = 1.0f / (1.0f + __expf(-c[mt][nt][0]));
            float s1 = 1.0f / (1.0f + __expf(-c[mt][nt][1]));
            float s2 = 1.0f / (1.0f + __expf(-c[mt][nt][2]));
            float s3 = 1.0f / (1.0f + __expf(-c[mt][nt][3]));
            *(float2*)&out[(size_t)(bm + r0) * NN + bn + c0 + nt * 8]     = make_float2(s0, s1);
            *(float2*)&out[(size_t)(bm + r0 + 8) * NN + bn + c0 + nt * 8] = make_float2(s2, s3);
            if (mirror) {
                S[r0][c0 + nt * 8]         = s0;
                S[r0][c0 + nt * 8 + 1]     = s1;
                S[r0 + 8][c0 + nt * 8]     = s2;
                S[r0 + 8][c0 + nt * 8 + 1] = s3;
            }
        }
    }
    if (mirror) {
        __syncthreads();
#pragma unroll 4
        for (int v = 0; v < 16; v++) {
            int idx = v * 256 + tid;
            int rr = idx >> 5, qc = (idx & 31) * 4;
            float4 o;
            o.x = S[qc + 0][rr];
            o.y = S[qc + 1][rr];
            o.z = S[qc + 2][rr];
            o.w = S[qc + 3][rr];
            *(float4*)&out[(size_t)(bn + rr) * NN + bm + qc] = o;
        }
    }
}

// ------ layer-2 GEMM (fp32 SIMT, 64x64 tiles) with fused alpha dots ----------
__global__ __launch_bounds__(256) void gemm2_a(const float* __restrict__ A,
                                               const float* __restrict__ B,
                                               const float* __restrict__ a_src,
                                               const float* __restrict__ a_dst,
                                               float* __restrict__ C,
                                               float* __restrict__ os,
                                               float* __restrict__ od) {
    __shared__ float As[16][64];
    __shared__ float Bs[16][64];
    const int tid = threadIdx.x;
    const int bm = blockIdx.x * 64;
    const int ty = tid >> 4, tx = tid & 15;
    float acc[4][4] = {};
    const int ra = tid >> 2, ka = (tid & 3) * 4;
    const int kb = tid >> 4, nb = (tid & 15) * 4;
    for (int k0 = 0; k0 < HF; k0 += 16) {
        float4 av = *(const float4*)&A[(size_t)(bm + ra) * HF + k0 + ka];
        float4 bv = *(const float4*)&B[(size_t)(k0 + kb) * OF + nb];
        As[ka + 0][ra] = av.x; As[ka + 1][ra] = av.y;
        As[ka + 2][ra] = av.z; As[ka + 3][ra] = av.w;
        *(float4*)&Bs[kb][nb] = bv;
        __syncthreads();
#pragma unroll
        for (int k = 0; k < 16; k++) {
            float4 a4 = *(const float4*)&As[k][ty * 4];
            float4 b4 = *(const float4*)&Bs[k][tx * 4];
            acc[0][0] += a4.x * b4.x; acc[0][1] += a4.x * b4.y;
            acc[0][2] += a4.x * b4.z; acc[0][3] += a4.x * b4.w;
            acc[1][0] += a4.y * b4.x; acc[1][1] += a4.y * b4.y;
            acc[1][2] += a4.y * b4.z; acc[1][3] += a4.y * b4.w;
            acc[2][0] += a4.z * b4.x; acc[2][1] += a4.z * b4.y;
            acc[2][2] += a4.z * b4.z; acc[2][3] += a4.z * b4.w;
            acc[3][0] += a4.w * b4.x; acc[3][1] += a4.w * b4.y;
            acc[3][2] += a4.w * b4.z; acc[3][3] += a4.w * b4.w;
        }
        __syncthreads();
    }
    float ss[4], sd[4];
#pragma unroll
    for (int i = 0; i < 4; i++) {
        float4 o = make_float4(acc[i][0], acc[i][1], acc[i][2], acc[i][3]);
        *(float4*)&C[(size_t)(bm + ty * 4 + i) * OF + tx * 4] = o;
        float a0 = __ldg(&a_src[tx * 4]),     d0 = __ldg(&a_dst[tx * 4]);
        float a1 = __ldg(&a_src[tx * 4 + 1]), d1 = __ldg(&a_dst[tx * 4 + 1]);
        float a2 = __ldg(&a_src[tx * 4 + 2]), d2 = __ldg(&a_dst[tx * 4 + 2]);
        float a3 = __ldg(&a_src[tx * 4 + 3]), d3 = __ldg(&a_dst[tx * 4 + 3]);
        ss[i] = acc[i][0] * a0 + acc[i][1] * a1 + acc[i][2] * a2 + acc[i][3] * a3;
        sd[i] = acc[i][0] * d0 + acc[i][1] * d1 + acc[i][2] * d2 + acc[i][3] * d3;
    }
#pragma unroll
    for (int o = 1; o <= 8; o <<= 1) {
#pragma unroll
        for (int i = 0; i < 4; i++) {
            ss[i] += __shfl_xor_sync(0xffffffffu, ss[i], o);
            sd[i] += __shfl_xor_sync(0xffffffffu, sd[i], o);
        }
    }
    if (tx == 0) {
#pragma unroll
        for (int i = 0; i < 4; i++) {
            os[bm + ty * 4 + i] = ss[i];
            od[bm + ty * 4 + i] = sd[i];
        }
    }
}

// ------------- CSR build (2 edges/thread; self loops folded in scan) ----------
__global__ void count_edges(const int* __restrict__ ei) {
    int i = blockIdx.x * blockDim.x + threadIdx.x;
    int2 d = *(const int2*)&ei[EE + i * 2];
    atomicAdd(&g_cnt[d.x], 1);
    atomicAdd(&g_cnt[d.y], 1);
}

__global__ __launch_bounds__(1024) void scan_kernel() {
    __shared__ int sh[1024];
    int tid = threadIdx.x;
    int local[8];
    int s = 0;
#pragma unroll
    for (int j = 0; j < 8; j++) { local[j] = g_cnt[tid * 8 + j] + 1; s += local[j]; }
    sh[tid] = s;
    __syncthreads();
    for (int off = 1; off < 1024; off <<= 1) {
        int v = (tid >= off) ? sh[tid - off] : 0;
        __syncthreads();
        sh[tid] += v;
        __syncthreads();
    }
    int run = sh[tid] - s;  // exclusive prefix
#pragma unroll
    for (int j = 0; j < 8; j++) {
        int node = tid * 8 + j;
        g_off[node] = run;
        g_srcs[run] = node;   // self loop goes first
        g_fill[node] = 1;
        run += local[j];
    }
    if (tid == 1023) g_off[NN] = run;
}

__global__ void scatter_edges(const int* __restrict__ ei) {
    int i = blockIdx.x * blockDim.x + threadIdx.x;
    int2 s = *(const int2*)&ei[i * 2];
    int2 d = *(const int2*)&ei[EE + i * 2];
    int p0 = g_off[d.x] + atomicAdd(&g_fill[d.x], 1); g_srcs[p0] = s.x;
    int p1 = g_off[d.y] + atomicAdd(&g_fill[d.y], 1); g_srcs[p1] = s.y;
}

// ------ GAT softmax-aggregate: float4 gather, group-per-edge (round-11) ------
template <int F, bool DO_ELU, bool EMIT_HILO>
__global__ __launch_bounds__(128) void gat_aggregate(const float* __restrict__ h,
                                                     const float* __restrict__ as,
                                                     const float* __restrict__ adv,
                                                     const float* __restrict__ bias,
                                                     float* __restrict__ out,
                                                     __nv_bfloat16* __restrict__ zh,
                                                     __nv_bfloat16* __restrict__ zl) {
    constexpr int G  = F / 4;      // lanes per edge (32 or 16)
    constexpr int NG = 128 / G;    // edges in parallel (4 or 8)
    const int dst = blockIdx.x;
    const int tid = threadIdx.x;
    const int grp = tid / G, lane = tid % G;
    const int beg = g_off[dst], end = g_off[dst + 1];
    const float ad = adv[dst];
    __shared__ float  wbuf[128];
    __shared__ int    sbuf[128];
    __shared__ float4 red4[128];
    __shared__ float  sred[NG];

    float4 acc = make_float4(0.f, 0.f, 0.f, 0.f);
    float s = 0.f;
    for (int base = beg; base < end; base += 128) {
        int j = base + tid;
        if (j < end) {
            int sidx = g_srcs[j];
            float e = as[sidx] + ad;
            e = e > 0.f ? e : 0.2f * e;
            wbuf[tid] = __expf(e);
            sbuf[tid] = sidx;
        }
        __syncthreads();
        int cnt = min(128, end - base);
#pragma unroll 4
        for (int c = grp; c < cnt; c += NG) {
            float w = wbuf[c];
            float4 hv = *(const float4*)&h[(size_t)sbuf[c] * F + lane * 4];
            s += w;
            acc.x += w * hv.x; acc.y += w * hv.y;
            acc.z += w * hv.z; acc.w += w * hv.w;
        }
        __syncthreads();
    }
    red4[tid] = acc;
    if (lane == 0) sred[grp] = s;
    __syncthreads();
    if (tid < G) {
        float4 a = red4[tid];
        float st = sred[0];
#pragma unroll
        for (int gg = 1; gg < NG; gg++) {
            float4 b = red4[gg * G + tid];
            a.x += b.x; a.y += b.y; a.z += b.z; a.w += b.w;
            st += sred[gg];
        }
        float inv = __fdividef(1.0f, st);
        float4 bi = *(const float4*)&bias[tid * 4];
        float4 v;
        v.x = a.x * inv + bi.x;
        v.y = a.y * inv + bi.y;
        v.z = a.z * inv + bi.z;
        v.w = a.w * inv + bi.w;
        if (DO_ELU) {
            v.x = v.x > 0.f ? v.x : (__expf(v.x) - 1.0f);
            v.y = v.y > 0.f ? v.y : (__expf(v.y) - 1.0f);
            v.z = v.z > 0.f ? v.z : (__expf(v.z) - 1.0f);
            v.w = v.w > 0.f ? v.w : (__expf(v.w) - 1.0f);
        }
        *(float4*)&out[(size_t)dst * F + tid * 4] = v;
        if (EMIT_HILO) {
            __nv_bfloat16 h0 = __float2bfloat16(v.x), h1 = __float2bfloat16(v.y);
            __nv_bfloat16 h2 = __float2bfloat16(v.z), h3 = __float2bfloat16(v.w);
            __nv_bfloat16 l0 = __float2bfloat16(v.x - __bfloat162float(h0));
            __nv_bfloat16 l1 = __float2bfloat16(v.y - __bfloat162float(h1));
            __nv_bfloat16 l2 = __float2bfloat16(v.z - __bfloat162float(h2));
            __nv_bfloat16 l3 = __float2bfloat16(v.w - __bfloat162float(h3));
            *(__nv_bfloat162*)&zh[(size_t)dst * F + tid * 4]     = __nv_bfloat162(h0, h1);
            *(__nv_bfloat162*)&zh[(size_t)dst * F + tid * 4 + 2] = __nv_bfloat162(h2, h3);
            *(__nv_bfloat162*)&zl[(size_t)dst * F + tid * 4]     = __nv_bfloat162(l0, l1);
            *(__nv_bfloat162*)&zl[(size_t)dst * F + tid * 4 + 2] = __nv_bfloat162(l2, l3);
        }
    }
}

// ---------------- student-t soft assignment q ---------------------------------
__global__ __launch_bounds__(128) void q_kernel(const float* __restrict__ z,
                                                const float* __restrict__ centers,
                                                float* __restrict__ q) {
    __shared__ float c[KCL * OF];
    for (int i = threadIdx.x; i < KCL * OF; i += blockDim.x) c[i] = centers[i];
    __syncthreads();
    int node = blockIdx.x * blockDim.x + threadIdx.x;
    if (node >= NN) return;
    float zr[OF];
#pragma unroll
    for (int f = 0; f < OF; f++) zr[f] = z[(size_t)node * OF + f];
    float qs[KCL];
    float tot = 0.f;
#pragma unroll
    for (int k = 0; k < KCL; k++) {
        float d2 = 0.f;
#pragma unroll
        for (int f = 0; f < OF; f++) {
            float d = zr[f] - c[k * OF + f];
            d2 += d * d;
        }
        float qk = 1.0f / (1.0f + d2);
        qs[k] = qk;
        tot += qk;
    }
    float inv = 1.0f / tot;
#pragma unroll
    for (int k = 0; k < KCL; k++) q[(size_t)node * KCL + k] = qs[k] * inv;
}

// ---------------- launcher ----------------------------------------------------
extern "C" void kernel_launch(void* const* d_in, const int* in_sizes, int n_in,
                              void* d_out, int out_size) {
    const float* x      = (const float*)d_in[0];
    const int*   ei     = (const int*)d_in[1];
    const float* W1     = (const float*)d_in[2];
    const float* a_src1 = (const float*)d_in[3];
    const float* a_dst1 = (const float*)d_in[4];
    const float* b1     = (const float*)d_in[5];
    const float* W2     = (const float*)d_in[6];
    const float* a_src2 = (const float*)d_in[7];
    const float* a_dst2 = (const float*)d_in[8];
    const float* b2     = (const float*)d_in[9];
    const float* centers= (const float*)d_in[10];

    float* out    = (float*)d_out;
    float* z_out  = out;                         // [NN, OF]
    float* apred  = out + (size_t)NN * OF;       // [NN, NN]
    float* q_out  = apred + (size_t)NN * NN;     // [NN, KCL]

    float *h1, *x2, *h2, *as1, *ad1, *as2, *ad2;
    int *cnt;
    __nv_bfloat16 *zh, *zl, *wh, *wl;
    cudaGetSymbolAddress((void**)&h1,  g_h1);
    cudaGetSymbolAddress((void**)&x2,  g_x2);
    cudaGetSymbolAddress((void**)&h2,  g_h2);
    cudaGetSymbolAddress((void**)&as1, g_as1);
    cudaGetSymbolAddress((void**)&ad1, g_ad1);
    cudaGetSymbolAddress((void**)&as2, g_as2);
    cudaGetSymbolAddress((void**)&ad2, g_ad2);
    cudaGetSymbolAddress((void**)&zh,  g_zhi);
    cudaGetSymbolAddress((void**)&zl,  g_zlo);
    cudaGetSymbolAddress((void**)&wh,  g_w1thi);
    cudaGetSymbolAddress((void**)&wl,  g_w1tlo);
    cudaGetSymbolAddress((void**)&cnt, g_cnt);

    cudaFuncSetAttribute(zzt_sym, cudaFuncAttributeMaxDynamicSharedMemorySize, ZT_TOTAL);
    cudaFuncSetAttribute(gemm1_fused, cudaFuncAttributeMaxDynamicSharedMemorySize, G1_TOTAL);

    static cudaStream_t s_side = nullptr;
    static cudaEvent_t ev_fork = nullptr, ev_csr = nullptr, ev_z = nullptr, ev_q = nullptr;
    if (s_side == nullptr) {
        cudaStreamCreateWithFlags(&s_side, cudaStreamNonBlocking);
        cudaEventCreateWithFlags(&ev_fork, cudaEventDisableTiming);
        cudaEventCreateWithFlags(&ev_csr,  cudaEventDisableTiming);
        cudaEventCreateWithFlags(&ev_z,    cudaEventDisableTiming);
        cudaEventCreateWithFlags(&ev_q,    cudaEventDisableTiming);
    }

    if (s_side != nullptr) {
        // ---- fork: CSR build on side stream, gemm1 path on main ----
        cudaEventRecord(ev_fork, 0);
        cudaStreamWaitEvent(s_side, ev_fork, 0);
        cudaMemsetAsync(cnt, 0, NN * sizeof(int), s_side);
        count_edges<<<EE / 2 / 256, 256, 0, s_side>>>(ei);
        scan_kernel<<<1, 1024, 0, s_side>>>();
        scatter_edges<<<EE / 2 / 256, 256, 0, s_side>>>(ei);
        cudaEventRecord(ev_csr, s_side);

        cvt_w1t<<<64, 256>>>(W1, wh, wl);
        gemm1_fused<<<NN / 64, 256, G1_TOTAL>>>(x, wh, wl, a_src1, a_dst1, h1, as1, ad1);

        // ---- join: aggregate needs CSR + gemm1 ----
        cudaStreamWaitEvent(0, ev_csr, 0);
        gat_aggregate<HF, true, false><<<NN, 128>>>(h1, as1, ad1, b1, x2, nullptr, nullptr);

        gemm2_a<<<NN / 64, 256>>>(x2, W2, a_src2, a_dst2, h2, as2, ad2);
        gat_aggregate<OF, false, true><<<NN, 128>>>(h2, as2, ad2, b2, z_out, zh, zl);

        // ---- fork: q on side (needs z), zzt on main (needs zh/zl) ----
        cudaEventRecord(ev_z, 0);
        cudaStreamWaitEvent(s_side, ev_z, 0);
        q_kernel<<<NN / 128, 128, 0, s_side>>>(z_out, centers, q_out);
        cudaEventRecord(ev_q, s_side);

        zzt_sym<<<NPAIR, 256, ZT_TOTAL>>>(zh, zl, apred);
        cudaStreamWaitEvent(0, ev_q, 0);
    } else {
        // fallback: sequential on default stream
        cudaMemsetAsync(cnt, 0, NN * sizeof(int));
        count_edges<<<EE / 2 / 256, 256>>>(ei);
        scan_kernel<<<1, 1024>>>();
        scatter_edges<<<EE / 2 / 256, 256>>>(ei);
        cvt_w1t<<<64, 256>>>(W1, wh, wl);
        gemm1_fused<<<NN / 64, 256, G1_TOTAL>>>(x, wh, wl, a_src1, a_dst1, h1, as1, ad1);
        gat_aggregate<HF, true, false><<<NN, 128>>>(h1, as1, ad1, b1, x2, nullptr, nullptr);
        gemm2_a<<<NN / 64, 256>>>(x2, W2, a_src2, a_dst2, h2, as2, ad2);
        gat_aggregate<OF, false, true><<<NN, 128>>>(h2, as2, ad2, b2, z_out, zh, zl);
        zzt_sym<<<NPAIR, 256, ZT_TOTAL>>>(zh, zl, apred);
        q_kernel<<<NN / 128, 128>>>(z_out, centers, q_out);
    }
}

// round 15
// speedup vs baseline: 1.0750x; 1.0620x over previous
#include <cuda_runtime.h>
#include <cuda_bf16.h>
#include <math.h>
#include <stdint.h>

#define NN 8192
#define EE 262144
#define ETOT 270336   /* EE + NN self loops */
#define INF_ 512
#define HF 128
#define OF 64
#define KCL 16
#define NTILE 64      /* NN / 128 */
#define NPAIR 2080    /* NTILE*(NTILE+1)/2 */

// ---------------- scratch (device globals: no allocation allowed) ------------
__device__ float g_h1[NN * HF];     // x @ W1
__device__ float g_x2[NN * HF];     // elu(gat1)
__device__ float g_h2[NN * OF];     // x2 @ W2
__device__ float g_as1[NN], g_ad1[NN];
__device__ float g_as2[NN], g_ad2[NN];
__device__ int   g_cnt[NN];
__device__ int   g_fill[NN];
__device__ int   g_off[NN + 1];
__device__ int   g_srcs[ETOT];
__device__ __nv_bfloat16 g_zhi[NN * OF];
__device__ __nv_bfloat16 g_zlo[NN * OF];
__device__ __nv_bfloat16 g_w1thi[HF * INF_];   // W1^T
__device__ __nv_bfloat16 g_w1tlo[HF * INF_];

// ---- streaming (evict-first) global stores ----------------------------------
__device__ __forceinline__ void stg_cs_f2(float* p, float a, float b) {
    asm volatile("st.global.cs.v2.f32 [%0], {%1, %2};" :: "l"(p), "f"(a), "f"(b) : "memory");
}
__device__ __forceinline__ void stg_cs_f4(float* p, float4 v) {
    asm volatile("st.global.cs.v4.f32 [%0], {%1, %2, %3, %4};"
                 :: "l"(p), "f"(v.x), "f"(v.y), "f"(v.z), "f"(v.w) : "memory");
}

// ---- W1 [512,128] -> W1T hi/lo [128,512], coalesced via 32x33 smem tiles ----
__global__ __launch_bounds__(256) void cvt_w1t(const float* __restrict__ W1,
                                               __nv_bfloat16* __restrict__ wh,
                                               __nv_bfloat16* __restrict__ wl) {
    __shared__ float tile[32][33];
    const int tx = threadIdx.x & 31, ty = threadIdx.x >> 5;   // 32 x 8
    const int nb = blockIdx.x & 3, kb = blockIdx.x >> 2;      // 4 n-tiles x 16 k-tiles
    const int k0 = kb * 32, n0 = nb * 32;
#pragma unroll
    for (int i = 0; i < 4; i++) {
        int kr = ty + i * 8;
        tile[kr][tx] = W1[(size_t)(k0 + kr) * HF + n0 + tx];
    }
    __syncthreads();
#pragma unroll
    for (int i = 0; i < 4; i++) {
        int nr = ty + i * 8;
        float v = tile[tx][nr];
        __nv_bfloat16 h = __float2bfloat16(v);
        size_t o = (size_t)(n0 + nr) * INF_ + k0 + tx;
        wh[o] = h;
        wl[o] = __float2bfloat16(v - __bfloat162float(h));
    }
}

// ---------------- HMMA + LDSM helpers ----------------------------------------
__device__ __forceinline__ void mma_bf16(float c[4], const uint32_t a[4],
                                         const uint32_t b[2]) {
    asm volatile(
        "mma.sync.aligned.m16n8k16.row.col.f32.bf16.bf16.f32 "
        "{%0,%1,%2,%3}, {%4,%5,%6,%7}, {%8,%9}, {%0,%1,%2,%3};"
        : "+f"(c[0]), "+f"(c[1]), "+f"(c[2]), "+f"(c[3])
        : "r"(a[0]), "r"(a[1]), "r"(a[2]), "r"(a[3]), "r"(b[0]), "r"(b[1]));
}

#define LDSM4(r, addr) \
    asm volatile("ldmatrix.sync.aligned.m8n8.x4.shared.b16 {%0,%1,%2,%3}, [%4];" \
                 : "=r"((r)[0]), "=r"((r)[1]), "=r"((r)[2]), "=r"((r)[3]) \
                 : "r"(addr))

#define ROWB 144                    // padded smem row stride in bytes (72 bf16)

// ===== gemm1: h1 = x @ W1 (fused fp32->hi/lo conversion + fused alphas) ======
#define G1_AHI 0
#define G1_ALO (64 * ROWB)
#define G1_BHI (2 * 64 * ROWB)
#define G1_BLO (G1_BHI + 128 * ROWB)
#define G1_TOTAL (G1_BHI + 2 * 128 * ROWB)   // 55296 B
#define G1_ALO_OFF (64 * ROWB)
#define G1_BLO_OFF (128 * ROWB)

__global__ __launch_bounds__(256) void gemm1_fused(const float* __restrict__ x,
                                                   const __nv_bfloat16* __restrict__ wh,
                                                   const __nv_bfloat16* __restrict__ wl,
                                                   const float* __restrict__ a_src,
                                                   const float* __restrict__ a_dst,
                                                   float* __restrict__ h1,
                                                   float* __restrict__ os,
                                                   float* __restrict__ od) {
    extern __shared__ char sm[];
    const uint32_t smb = (uint32_t)__cvta_generic_to_shared(sm);
    __shared__ float red[2][2][64];   // [wn][s|d][local row]
    const int tid = threadIdx.x;
    const int bm = blockIdx.x * 64;
    const int wid = tid >> 5, lane = tid & 31;
    const int wm = wid & 3, wn = wid >> 2;
    const int g = lane >> 2, tg = lane & 3;
    const int sub = lane >> 3, lrow = lane & 7;

    float c[8][4] = {};

    const uint32_t aAddr = smb + G1_AHI +
        (uint32_t)(wm * 16 + (sub & 1) * 8 + lrow) * ROWB + (sub >> 1) * 16;
    const uint32_t bAddr = smb + G1_BHI +
        (uint32_t)(wn * 64 + (sub >> 1) * 8 + lrow) * ROWB + (sub & 1) * 16;

    for (int kc = 0; kc < 8; kc++) {
        const int k0 = kc * 64;
#pragma unroll
        for (int t = tid; t < 1024; t += 256) {
            int r = t >> 4, c4 = t & 15;
            float4 v = *(const float4*)&x[(size_t)(bm + r) * INF_ + k0 + c4 * 4];
            __nv_bfloat16 h0 = __float2bfloat16(v.x), h1v = __float2bfloat16(v.y);
            __nv_bfloat16 h2 = __float2bfloat16(v.z), h3 = __float2bfloat16(v.w);
            __nv_bfloat16 l0 = __float2bfloat16(v.x - __bfloat162float(h0));
            __nv_bfloat16 l1 = __float2bfloat16(v.y - __bfloat162float(h1v));
            __nv_bfloat16 l2 = __float2bfloat16(v.z - __bfloat162float(h2));
            __nv_bfloat16 l3 = __float2bfloat16(v.w - __bfloat162float(h3));
            char* pa = sm + G1_AHI + r * ROWB + c4 * 8;
            *(__nv_bfloat162*)(pa)     = __nv_bfloat162(h0, h1v);
            *(__nv_bfloat162*)(pa + 4) = __nv_bfloat162(h2, h3);
            char* pl = sm + G1_ALO + r * ROWB + c4 * 8;
            *(__nv_bfloat162*)(pl)     = __nv_bfloat162(l0, l1);
            *(__nv_bfloat162*)(pl + 4) = __nv_bfloat162(l2, l3);
        }
#pragma unroll
        for (int t = tid; t < 1024; t += 256) {
            int r = t >> 3, cc = t & 7;
            *(uint4*)(sm + G1_BHI + r * ROWB + cc * 16) =
                *(const uint4*)(wh + (size_t)r * INF_ + k0 + cc * 8);
            *(uint4*)(sm + G1_BLO + r * ROWB + cc * 16) =
                *(const uint4*)(wl + (size_t)r * INF_ + k0 + cc * 8);
        }
        __syncthreads();

#pragma unroll
        for (int k = 0; k < 4; k++) {
            const int kb = k * 32;
            uint32_t ah[4], al[4];
            LDSM4(ah, aAddr + kb);
            LDSM4(al, aAddr + G1_ALO_OFF + kb);
#pragma unroll
            for (int pp = 0; pp < 4; pp++) {
                uint32_t bh[4], bl[4];
                LDSM4(bh, bAddr + pp * (16 * ROWB) + kb);
                LDSM4(bl, bAddr + pp * (16 * ROWB) + G1_BLO_OFF + kb);
                const int n0 = 2 * pp, n1 = 2 * pp + 1;
                mma_bf16(c[n0], ah, &bh[0]);
                mma_bf16(c[n1], ah, &bh[2]);
                mma_bf16(c[n0], ah, &bl[0]);
                mma_bf16(c[n1], ah, &bl[2]);
                mma_bf16(c[n0], al, &bh[0]);
                mma_bf16(c[n1], al, &bh[2]);
            }
        }
        __syncthreads();
    }

    const int r0 = bm + wm * 16 + g;
    const int col0 = wn * 64 + tg * 2;
    float ssA = 0.f, sdA = 0.f, ssB = 0.f, sdB = 0.f;
#pragma unroll
    for (int nt = 0; nt < 8; nt++) {
        *(float2*)&h1[(size_t)r0 * HF + col0 + nt * 8]       = make_float2(c[nt][0], c[nt][1]);
        *(float2*)&h1[(size_t)(r0 + 8) * HF + col0 + nt * 8] = make_float2(c[nt][2], c[nt][3]);
        float a0 = __ldg(&a_src[col0 + nt * 8]), a1 = __ldg(&a_src[col0 + nt * 8 + 1]);
        float d0 = __ldg(&a_dst[col0 + nt * 8]), d1 = __ldg(&a_dst[col0 + nt * 8 + 1]);
        ssA += c[nt][0] * a0 + c[nt][1] * a1;
        sdA += c[nt][0] * d0 + c[nt][1] * d1;
        ssB += c[nt][2] * a0 + c[nt][3] * a1;
        sdB += c[nt][2] * d0 + c[nt][3] * d1;
    }
#pragma unroll
    for (int o = 1; o <= 2; o <<= 1) {
        ssA += __shfl_xor_sync(0xffffffffu, ssA, o);
        sdA += __shfl_xor_sync(0xffffffffu, sdA, o);
        ssB += __shfl_xor_sync(0xffffffffu, ssB, o);
        sdB += __shfl_xor_sync(0xffffffffu, sdB, o);
    }
    const int rowA = wm * 16 + g, rowB = rowA + 8;
    if (tg == 0) {
        red[wn][0][rowA] = ssA; red[wn][0][rowB] = ssB;
        red[wn][1][rowA] = sdA; red[wn][1][rowB] = sdB;
    }
    __syncthreads();
    if (tid < 64) {
        os[bm + tid] = red[0][0][tid] + red[1][0][tid];
        od[bm + tid] = red[0][1][tid] + red[1][1][tid];
    }
}

// ============ A_pred = sigmoid(z z^T): ldmatrix + fused hi/lo mainloop =======
#define TILE_B (128 * ROWB)
#define ZT_AHI 0
#define ZT_ALO TILE_B
#define ZT_BHI (2 * TILE_B)
#define ZT_BLO (3 * TILE_B)
#define ZT_TOTAL (4 * TILE_B)       // 73728 B; mirror stage reuses it

__global__ __launch_bounds__(256, 2) void zzt_sym(const __nv_bfloat16* __restrict__ zh,
                                                  const __nv_bfloat16* __restrict__ zl,
                                                  float* __restrict__ out) {
    extern __shared__ char sm[];
    const uint32_t smb = (uint32_t)__cvta_generic_to_shared(sm);
    const int tid = threadIdx.x;

    int p = blockIdx.x;
    int bi = (int)((2.0f * NTILE + 1.0f -
                    sqrtf((2.0f * NTILE + 1.0f) * (2.0f * NTILE + 1.0f) - 8.0f * p)) * 0.5f);
    if (bi < 0) bi = 0;
    if (bi > NTILE - 1) bi = NTILE - 1;
    while (bi > 0 && bi * NTILE - bi * (bi - 1) / 2 > p) bi--;
    while ((bi + 1) * NTILE - (bi + 1) * bi / 2 <= p) bi++;
    const int bj = bi + (p - (bi * NTILE - bi * (bi - 1) / 2));
    const int bm = bi * 128, bn = bj * 128;

#pragma unroll
    for (int t = tid; t < 1024; t += 256) {
        int r = t >> 3, c = t & 7;
        *(uint4*)(sm + ZT_AHI + r * ROWB + c * 16) = *(const uint4*)(zh + (size_t)(bm + r) * 64 + c * 8);
        *(uint4*)(sm + ZT_ALO + r * ROWB + c * 16) = *(const uint4*)(zl + (size_t)(bm + r) * 64 + c * 8);
        *(uint4*)(sm + ZT_BHI + r * ROWB + c * 16) = *(const uint4*)(zh + (size_t)(bn + r) * 64 + c * 8);
        *(uint4*)(sm + ZT_BLO + r * ROWB + c * 16) = *(const uint4*)(zl + (size_t)(bn + r) * 64 + c * 8);
    }
    __syncthreads();

    const int wid = tid >> 5, lane = tid & 31;
    const int wm = wid & 3, wn = wid >> 2;
    const int sub = lane >> 3, lrow = lane & 7;

    const uint32_t aAddr0 = smb + ZT_AHI +
        (uint32_t)(wm * 32 + (sub & 1) * 8 + lrow) * ROWB + (sub >> 1) * 16;
    const uint32_t aAddr1 = aAddr0 + 16 * ROWB;
    const uint32_t bAddr = smb + ZT_BHI +
        (uint32_t)(wn * 64 + (sub >> 1) * 8 + lrow) * ROWB + (sub & 1) * 16;

    float c[2][8][4] = {};

#pragma unroll
    for (int k = 0; k < 4; k++) {
        const int kb = k * 32;
        uint32_t ah[2][4], al[2][4];
        LDSM4(ah[0], aAddr0 + kb);
        LDSM4(ah[1], aAddr1 + kb);
        LDSM4(al[0], aAddr0 + TILE_B + kb);
        LDSM4(al[1], aAddr1 + TILE_B + kb);
#pragma unroll
        for (int pp = 0; pp < 4; pp++) {
            uint32_t bh[4], bl[4];
            LDSM4(bh, bAddr + pp * (16 * ROWB) + kb);
            LDSM4(bl, bAddr + pp * (16 * ROWB) + TILE_B + kb);
            const int n0 = 2 * pp, n1 = 2 * pp + 1;
#pragma unroll
            for (int mt = 0; mt < 2; mt++) {
                mma_bf16(c[mt][n0], ah[mt], &bh[0]);
                mma_bf16(c[mt][n1], ah[mt], &bh[2]);
                mma_bf16(c[mt][n0], ah[mt], &bl[0]);
                mma_bf16(c[mt][n1], ah[mt], &bl[2]);
                mma_bf16(c[mt][n0], al[mt], &bh[0]);
                mma_bf16(c[mt][n1], al[mt], &bh[2]);
            }
        }
    }

    __syncthreads();
    float (*S)[129] = (float(*)[129])sm;
    const bool mirror = (bi != bj);
    const int g = lane >> 2, tg = lane & 3;

#pragma unroll
    for (int mt = 0; mt < 2; mt++) {
        const int r0 = wm * 32 + mt * 16 + g;
        const int c0 = wn * 64 + tg * 2;
#pragma unroll
        for (int nt = 0; nt < 8; nt++) {
            float s0 = 1.0f / (1.0f + __expf(-c[mt][nt][0]));
            float s1 = 1.0f / (1.0f + __expf(-c[mt][nt][1]));
            float s2 = 1.0f / (1.0f + __expf(-c[mt][nt][2]));
            float s3 = 1.0f / (1.0f + __expf(-c[mt][nt][3]));
            stg_cs_f2(&out[(size_t)(bm + r0) * NN + bn + c0 + nt * 8], s0, s1);
            stg_cs_f2(&out[(size_t)(bm + r0 + 8) * NN + bn + c0 + nt * 8], s2, s3);
            if (mirror) {
                S[r0][c0 + nt * 8]         = s0;
                S[r0][c0 + nt * 8 + 1]     = s1;
                S[r0 + 8][c0 + nt * 8]     = s2;
                S[r0 + 8][c0 + nt * 8 + 1] = s3;
            }
        }
    }
    if (mirror) {
        __syncthreads();
#pragma unroll 4
        for (int v = 0; v < 16; v++) {
            int idx = v * 256 + tid;
            int rr = idx >> 5, qc = (idx & 31) * 4;
            float4 o;
            o.x = S[qc + 0][rr];
            o.y = S[qc + 1][rr];
            o.z = S[qc + 2][rr];
            o.w = S[qc + 3][rr];
            stg_cs_f4(&out[(size_t)(bn + rr) * NN + bm + qc], o);
        }
    }
}

// ------ layer-2 GEMM (fp32 SIMT, 64x64 tiles) with fused alpha dots ----------
__global__ __launch_bounds__(256) void gemm2_a(const float* __restrict__ A,
                                               const float* __restrict__ B,
                                               const float* __restrict__ a_src,
                                               const float* __restrict__ a_dst,
                                               float* __restrict__ C,
                                               float* __restrict__ os,
                                               float* __restrict__ od) {
    __shared__ float As[16][64];
    __shared__ float Bs[16][64];
    const int tid = threadIdx.x;
    const int bm = blockIdx.x * 64;
    const int ty = tid >> 4, tx = tid & 15;
    float acc[4][4] = {};
    const int ra = tid >> 2, ka = (tid & 3) * 4;
    const int kb = tid >> 4, nb = (tid & 15) * 4;
    for (int k0 = 0; k0 < HF; k0 += 16) {
        float4 av = *(const float4*)&A[(size_t)(bm + ra) * HF + k0 + ka];
        float4 bv = *(const float4*)&B[(size_t)(k0 + kb) * OF + nb];
        As[ka + 0][ra] = av.x; As[ka + 1][ra] = av.y;
        As[ka + 2][ra] = av.z; As[ka + 3][ra] = av.w;
        *(float4*)&Bs[kb][nb] = bv;
        __syncthreads();
#pragma unroll
        for (int k = 0; k < 16; k++) {
            float4 a4 = *(const float4*)&As[k][ty * 4];
            float4 b4 = *(const float4*)&Bs[k][tx * 4];
            acc[0][0] += a4.x * b4.x; acc[0][1] += a4.x * b4.y;
            acc[0][2] += a4.x * b4.z; acc[0][3] += a4.x * b4.w;
            acc[1][0] += a4.y * b4.x; acc[1][1] += a4.y * b4.y;
            acc[1][2] += a4.y * b4.z; acc[1][3] += a4.y * b4.w;
            acc[2][0] += a4.z * b4.x; acc[2][1] += a4.z * b4.y;
            acc[2][2] += a4.z * b4.z; acc[2][3] += a4.z * b4.w;
            acc[3][0] += a4.w * b4.x; acc[3][1] += a4.w * b4.y;
            acc[3][2] += a4.w * b4.z; acc[3][3] += a4.w * b4.w;
        }
        __syncthreads();
    }
    float ss[4], sd[4];
#pragma unroll
    for (int i = 0; i < 4; i++) {
        float4 o = make_float4(acc[i][0], acc[i][1], acc[i][2], acc[i][3]);
        *(float4*)&C[(size_t)(bm + ty * 4 + i) * OF + tx * 4] = o;
        float a0 = __ldg(&a_src[tx * 4]),     d0 = __ldg(&a_dst[tx * 4]);
        float a1 = __ldg(&a_src[tx * 4 + 1]), d1 = __ldg(&a_dst[tx * 4 + 1]);
        float a2 = __ldg(&a_src[tx * 4 + 2]), d2 = __ldg(&a_dst[tx * 4 + 2]);
        float a3 = __ldg(&a_src[tx * 4 + 3]), d3 = __ldg(&a_dst[tx * 4 + 3]);
        ss[i] = acc[i][0] * a0 + acc[i][1] * a1 + acc[i][2] * a2 + acc[i][3] * a3;
        sd[i] = acc[i][0] * d0 + acc[i][1] * d1 + acc[i][2] * d2 + acc[i][3] * d3;
    }
#pragma unroll
    for (int o = 1; o <= 8; o <<= 1) {
#pragma unroll
        for (int i = 0; i < 4; i++) {
            ss[i] += __shfl_xor_sync(0xffffffffu, ss[i], o);
            sd[i] += __shfl_xor_sync(0xffffffffu, sd[i], o);
        }
    }
    if (tx == 0) {
#pragma unroll
        for (int i = 0; i < 4; i++) {
            os[bm + ty * 4 + i] = ss[i];
            od[bm + ty * 4 + i] = sd[i];
        }
    }
}

// ---------------- CSR build (1 edge/thread; self loops folded in scan) --------
__global__ void count_edges(const int* __restrict__ ei) {
    int i = blockIdx.x * blockDim.x + threadIdx.x;
    atomicAdd(&g_cnt[ei[EE + i]], 1);
}

__global__ __launch_bounds__(1024) void scan_kernel() {
    __shared__ int sh[1024];
    int tid = threadIdx.x;
    int local[8];
    int s = 0;
#pragma unroll
    for (int j = 0; j < 8; j++) { local[j] = g_cnt[tid * 8 + j] + 1; s += local[j]; }
    sh[tid] = s;
    __syncthreads();
    for (int off = 1; off < 1024; off <<= 1) {
        int v = (tid >= off) ? sh[tid - off] : 0;
        __syncthreads();
        sh[tid] += v;
        __syncthreads();
    }
    int run = sh[tid] - s;  // exclusive prefix
#pragma unroll
    for (int j = 0; j < 8; j++) {
        int node = tid * 8 + j;
        g_off[node] = run;
        g_srcs[run] = node;   // self loop goes first
        g_fill[node] = 1;
        run += local[j];
    }
    if (tid == 1023) g_off[NN] = run;
}

__global__ void scatter_edges(const int* __restrict__ ei) {
    int i = blockIdx.x * blockDim.x + threadIdx.x;
    int src = ei[i], dst = ei[EE + i];
    int pos = g_off[dst] + atomicAdd(&g_fill[dst], 1);
    g_srcs[pos] = src;
}

// ------ GAT softmax-aggregate: float4 gather, group-per-edge -----------------
template <int F, bool DO_ELU, bool EMIT_HILO>
__global__ __launch_bounds__(128) void gat_aggregate(const float* __restrict__ h,
                                                     const float* __restrict__ as,
                                                     const float* __restrict__ adv,
                                                     const float* __restrict__ bias,
                                                     float* __restrict__ out,
                                                     __nv_bfloat16* __restrict__ zh,
                                                     __nv_bfloat16* __restrict__ zl) {
    constexpr int G  = F / 4;      // lanes per edge (32 or 16)
    constexpr int NG = 128 / G;    // edges in parallel (4 or 8)
    const int dst = blockIdx.x;
    const int tid = threadIdx.x;
    const int grp = tid / G, lane = tid % G;
    const int beg = g_off[dst], end = g_off[dst + 1];
    const float ad = adv[dst];
    __shared__ float  wbuf[128];
    __shared__ int    sbuf[128];
    __shared__ float4 red4[128];
    __shared__ float  sred[NG];

    float4 acc = make_float4(0.f, 0.f, 0.f, 0.f);
    float s = 0.f;
    for (int base = beg; base < end; base += 128) {
        int j = base + tid;
        if (j < end) {
            int sidx = g_srcs[j];
            float e = as[sidx] + ad;
            e = e > 0.f ? e : 0.2f * e;
            wbuf[tid] = __expf(e);
            sbuf[tid] = sidx;
        }
        __syncthreads();
        int cnt = min(128, end - base);
#pragma unroll 4
        for (int c = grp; c < cnt; c += NG) {
            float w = wbuf[c];
            float4 hv = *(const float4*)&h[(size_t)sbuf[c] * F + lane * 4];
            s += w;
            acc.x += w * hv.x; acc.y += w * hv.y;
            acc.z += w * hv.z; acc.w += w * hv.w;
        }
        __syncthreads();
    }
    red4[tid] = acc;
    if (lane == 0) sred[grp] = s;
    __syncthreads();
    if (tid < G) {
        float4 a = red4[tid];
        float st = sred[0];
#pragma unroll
        for (int gg = 1; gg < NG; gg++) {
            float4 b = red4[gg * G + tid];
            a.x += b.x; a.y += b.y; a.z += b.z; a.w += b.w;
            st += sred[gg];
        }
        float inv = __fdividef(1.0f, st);
        float4 bi = *(const float4*)&bias[tid * 4];
        float4 v;
        v.x = a.x * inv + bi.x;
        v.y = a.y * inv + bi.y;
        v.z = a.z * inv + bi.z;
        v.w = a.w * inv + bi.w;
        if (DO_ELU) {
            v.x = v.x > 0.f ? v.x : (__expf(v.x) - 1.0f);
            v.y = v.y > 0.f ? v.y : (__expf(v.y) - 1.0f);
            v.z = v.z > 0.f ? v.z : (__expf(v.z) - 1.0f);
            v.w = v.w > 0.f ? v.w : (__expf(v.w) - 1.0f);
        }
        *(float4*)&out[(size_t)dst * F + tid * 4] = v;
        if (EMIT_HILO) {
            __nv_bfloat16 h0 = __float2bfloat16(v.x), h1 = __float2bfloat16(v.y);
            __nv_bfloat16 h2 = __float2bfloat16(v.z), h3 = __float2bfloat16(v.w);
            __nv_bfloat16 l0 = __float2bfloat16(v.x - __bfloat162float(h0));
            __nv_bfloat16 l1 = __float2bfloat16(v.y - __bfloat162float(h1));
            __nv_bfloat16 l2 = __float2bfloat16(v.z - __bfloat162float(h2));
            __nv_bfloat16 l3 = __float2bfloat16(v.w - __bfloat162float(h3));
            *(__nv_bfloat162*)&zh[(size_t)dst * F + tid * 4]     = __nv_bfloat162(h0, h1);
            *(__nv_bfloat162*)&zh[(size_t)dst * F + tid * 4 + 2] = __nv_bfloat162(h2, h3);
            *(__nv_bfloat162*)&zl[(size_t)dst * F + tid * 4]     = __nv_bfloat162(l0, l1);
            *(__nv_bfloat162*)&zl[(size_t)dst * F + tid * 4 + 2] = __nv_bfloat162(l2, l3);
        }
    }
}

// ---------------- student-t soft assignment q ---------------------------------
__global__ __launch_bounds__(128) void q_kernel(const float* __restrict__ z,
                                                const float* __restrict__ centers,
                                                float* __restrict__ q) {
    __shared__ float c[KCL * OF];
    for (int i = threadIdx.x; i < KCL * OF; i += blockDim.x) c[i] = centers[i];
    __syncthreads();
    int node = blockIdx.x * blockDim.x + threadIdx.x;
    if (node >= NN) return;
    float zr[OF];
#pragma unroll
    for (int f = 0; f < OF; f++) zr[f] = z[(size_t)node * OF + f];
    float qs[KCL];
    float tot = 0.f;
#pragma unroll
    for (int k = 0; k < KCL; k++) {
        float d2 = 0.f;
#pragma unroll
        for (int f = 0; f < OF; f++) {
            float d = zr[f] - c[k * OF + f];
            d2 += d * d;
        }
        float qk = 1.0f / (1.0f + d2);
        qs[k] = qk;
        tot += qk;
    }
    float inv = 1.0f / tot;
#pragma unroll
    for (int k = 0; k < KCL; k++) q[(size_t)node * KCL + k] = qs[k] * inv;
}

// ---------------- launcher ----------------------------------------------------
extern "C" void kernel_launch(void* const* d_in, const int* in_sizes, int n_in,
                              void* d_out, int out_size) {
    const float* x      = (const float*)d_in[0];
    const int*   ei     = (const int*)d_in[1];
    const float* W1     = (const float*)d_in[2];
    const float* a_src1 = (const float*)d_in[3];
    const float* a_dst1 = (const float*)d_in[4];
    const float* b1     = (const float*)d_in[5];
    const float* W2     = (const float*)d_in[6];
    const float* a_src2 = (const float*)d_in[7];
    const float* a_dst2 = (const float*)d_in[8];
    const float* b2     = (const float*)d_in[9];
    const float* centers= (const float*)d_in[10];

    float* out    = (float*)d_out;
    float* z_out  = out;                         // [NN, OF]
    float* apred  = out + (size_t)NN * OF;       // [NN, NN]
    float* q_out  = apred + (size_t)NN * NN;     // [NN, KCL]

    float *h1, *x2, *h2, *as1, *ad1, *as2, *ad2;
    int *cnt;
    __nv_bfloat16 *zh, *zl, *wh, *wl;
    cudaGetSymbolAddress((void**)&h1,  g_h1);
    cudaGetSymbolAddress((void**)&x2,  g_x2);
    cudaGetSymbolAddress((void**)&h2,  g_h2);
    cudaGetSymbolAddress((void**)&as1, g_as1);
    cudaGetSymbolAddress((void**)&ad1, g_ad1);
    cudaGetSymbolAddress((void**)&as2, g_as2);
    cudaGetSymbolAddress((void**)&ad2, g_ad2);
    cudaGetSymbolAddress((void**)&zh,  g_zhi);
    cudaGetSymbolAddress((void**)&zl,  g_zlo);
    cudaGetSymbolAddress((void**)&wh,  g_w1thi);
    cudaGetSymbolAddress((void**)&wl,  g_w1tlo);
    cudaGetSymbolAddress((void**)&cnt, g_cnt);

    cudaFuncSetAttribute(zzt_sym, cudaFuncAttributeMaxDynamicSharedMemorySize, ZT_TOTAL);
    cudaFuncSetAttribute(gemm1_fused, cudaFuncAttributeMaxDynamicSharedMemorySize, G1_TOTAL);

    static cudaStream_t s_side = nullptr;
    static cudaEvent_t ev_fork = nullptr, ev_csr = nullptr, ev_z = nullptr, ev_q = nullptr;
    if (s_side == nullptr) {
        cudaStreamCreateWithFlags(&s_side, cudaStreamNonBlocking);
        cudaEventCreateWithFlags(&ev_fork, cudaEventDisableTiming);
        cudaEventCreateWithFlags(&ev_csr,  cudaEventDisableTiming);
        cudaEventCreateWithFlags(&ev_z,    cudaEventDisableTiming);
        cudaEventCreateWithFlags(&ev_q,    cudaEventDisableTiming);
    }

    if (s_side != nullptr) {
        // ---- fork: CSR build on side stream, gemm1 path on main ----
        cudaEventRecord(ev_fork, 0);
        cudaStreamWaitEvent(s_side, ev_fork, 0);
        cudaMemsetAsync(cnt, 0, NN * sizeof(int), s_side);
        count_edges<<<EE / 256, 256, 0, s_side>>>(ei);
        scan_kernel<<<1, 1024, 0, s_side>>>();
        scatter_edges<<<EE / 256, 256, 0, s_side>>>(ei);
        cudaEventRecord(ev_csr, s_side);

        cvt_w1t<<<64, 256>>>(W1, wh, wl);
        gemm1_fused<<<NN / 64, 256, G1_TOTAL>>>(x, wh, wl, a_src1, a_dst1, h1, as1, ad1);

        // ---- join: aggregate needs CSR + gemm1 ----
        cudaStreamWaitEvent(0, ev_csr, 0);
        gat_aggregate<HF, true, false><<<NN, 128>>>(h1, as1, ad1, b1, x2, nullptr, nullptr);

        gemm2_a<<<NN / 64, 256>>>(x2, W2, a_src2, a_dst2, h2, as2, ad2);
        gat_aggregate<OF, false, true><<<NN, 128>>>(h2, as2, ad2, b2, z_out, zh, zl);

        // ---- fork: q on side (needs z), zzt on main (needs zh/zl) ----
        cudaEventRecord(ev_z, 0);
        cudaStreamWaitEvent(s_side, ev_z, 0);
        q_kernel<<<NN / 128, 128, 0, s_side>>>(z_out, centers, q_out);
        cudaEventRecord(ev_q, s_side);

        zzt_sym<<<NPAIR, 256, ZT_TOTAL>>>(zh, zl, apred);
        cudaStreamWaitEvent(0, ev_q, 0);
    } else {
        // fallback: sequential on default stream
        cudaMemsetAsync(cnt, 0, NN * sizeof(int));
        count_edges<<<EE / 256, 256>>>(ei);
        scan_kernel<<<1, 1024>>>();
        scatter_edges<<<EE / 256, 256>>>(ei);
        cvt_w1t<<<64, 256>>>(W1, wh, wl);
        gemm1_fused<<<NN / 64, 256, G1_TOTAL>>>(x, wh, wl, a_src1, a_dst1, h1, as1, ad1);
        gat_aggregate<HF, true, false><<<NN, 128>>>(h1, as1, ad1, b1, x2, nullptr, nullptr);
        gemm2_a<<<NN / 64, 256>>>(x2, W2, a_src2, a_dst2, h2, as2, ad2);
        gat_aggregate<OF, false, true><<<NN, 128>>>(h2, as2, ad2, b2, z_out, zh, zl);
        zzt_sym<<<NPAIR, 256, ZT_TOTAL>>>(zh, zl, apred);
        q_kernel<<<NN / 128, 128>>>(z_out, centers, q_out);
    }
}

// round 17
// speedup vs baseline: 1.0752x; 1.0002x over previous
#include <cuda_runtime.h>
#include <cuda_bf16.h>
#include <math.h>
#include <stdint.h>

#define NN 8192
#define EE 262144
#define ETOT 270336   /* EE + NN self loops */
#define INF_ 512
#define HF 128
#define OF 64
#define KCL 16
#define NTILE 64      /* NN / 128 */
#define NPAIR 2080    /* NTILE*(NTILE+1)/2 */

// ---------------- scratch (device globals: no allocation allowed) ------------
__device__ float g_h1[NN * HF];     // x @ W1
__device__ float g_x2[NN * HF];     // elu(gat1)
__device__ float g_h2[NN * OF];     // x2 @ W2
__device__ float g_as1[NN], g_ad1[NN];
__device__ float g_as2[NN], g_ad2[NN];
__device__ int   g_cnt[NN];         // zero at module load; scan re-zeroes each run
__device__ int   g_fill[NN];
__device__ int   g_off[NN + 1];
__device__ int   g_srcs[ETOT];
__device__ __nv_bfloat16 g_zhi[NN * OF];
__device__ __nv_bfloat16 g_zlo[NN * OF];
__device__ __nv_bfloat16 g_w1thi[HF * INF_];   // W1^T
__device__ __nv_bfloat16 g_w1tlo[HF * INF_];

// ---- streaming (evict-first) global stores ----------------------------------
__device__ __forceinline__ void stg_cs_f2(float* p, float a, float b) {
    asm volatile("st.global.cs.v2.f32 [%0], {%1, %2};" :: "l"(p), "f"(a), "f"(b) : "memory");
}
__device__ __forceinline__ void stg_cs_f4(float* p, float4 v) {
    asm volatile("st.global.cs.v4.f32 [%0], {%1, %2, %3, %4};"
                 :: "l"(p), "f"(v.x), "f"(v.y), "f"(v.z), "f"(v.w) : "memory");
}

// ---- W1 [512,128] -> W1T hi/lo [128,512], coalesced via 32x33 smem tiles ----
__global__ __launch_bounds__(256) void cvt_w1t(const float* __restrict__ W1,
                                               __nv_bfloat16* __restrict__ wh,
                                               __nv_bfloat16* __restrict__ wl) {
    __shared__ float tile[32][33];
    const int tx = threadIdx.x & 31, ty = threadIdx.x >> 5;   // 32 x 8
    const int nb = blockIdx.x & 3, kb = blockIdx.x >> 2;      // 4 n-tiles x 16 k-tiles
    const int k0 = kb * 32, n0 = nb * 32;
#pragma unroll
    for (int i = 0; i < 4; i++) {
        int kr = ty + i * 8;
        tile[kr][tx] = W1[(size_t)(k0 + kr) * HF + n0 + tx];
    }
    __syncthreads();
#pragma unroll
    for (int i = 0; i < 4; i++) {
        int nr = ty + i * 8;
        float v = tile[tx][nr];
        __nv_bfloat16 h = __float2bfloat16(v);
        size_t o = (size_t)(n0 + nr) * INF_ + k0 + tx;
        wh[o] = h;
        wl[o] = __float2bfloat16(v - __bfloat162float(h));
    }
}

// ---------------- HMMA + LDSM helpers ----------------------------------------
__device__ __forceinline__ void mma_bf16(float c[4], const uint32_t a[4],
                                         const uint32_t b[2]) {
    asm volatile(
        "mma.sync.aligned.m16n8k16.row.col.f32.bf16.bf16.f32 "
        "{%0,%1,%2,%3}, {%4,%5,%6,%7}, {%8,%9}, {%0,%1,%2,%3};"
        : "+f"(c[0]), "+f"(c[1]), "+f"(c[2]), "+f"(c[3])
        : "r"(a[0]), "r"(a[1]), "r"(a[2]), "r"(a[3]), "r"(b[0]), "r"(b[1]));
}

#define LDSM4(r, addr) \
    asm volatile("ldmatrix.sync.aligned.m8n8.x4.shared.b16 {%0,%1,%2,%3}, [%4];" \
                 : "=r"((r)[0]), "=r"((r)[1]), "=r"((r)[2]), "=r"((r)[3]) \
                 : "r"(addr))

#define ROWB 144                    // padded smem row stride in bytes (72 bf16)

// ===== gemm1: h1 = x @ W1 (fused fp32->hi/lo conversion + fused alphas) ======
#define G1_AHI 0
#define G1_ALO (64 * ROWB)
#define G1_BHI (2 * 64 * ROWB)
#define G1_BLO (G1_BHI + 128 * ROWB)
#define G1_TOTAL (G1_BHI + 2 * 128 * ROWB)   // 55296 B
#define G1_ALO_OFF (64 * ROWB)
#define G1_BLO_OFF (128 * ROWB)

__global__ __launch_bounds__(256) void gemm1_fused(const float* __restrict__ x,
                                                   const __nv_bfloat16* __restrict__ wh,
                                                   const __nv_bfloat16* __restrict__ wl,
                                                   const float* __restrict__ a_src,
                                                   const float* __restrict__ a_dst,
                                                   float* __restrict__ h1,
                                                   float* __restrict__ os,
                                                   float* __restrict__ od) {
    extern __shared__ char sm[];
    const uint32_t smb = (uint32_t)__cvta_generic_to_shared(sm);
    __shared__ float red[2][2][64];   // [wn][s|d][local row]
    const int tid = threadIdx.x;
    const int bm = blockIdx.x * 64;
    const int wid = tid >> 5, lane = tid & 31;
    const int wm = wid & 3, wn = wid >> 2;
    const int g = lane >> 2, tg = lane & 3;
    const int sub = lane >> 3, lrow = lane & 7;

    float c[8][4] = {};

    const uint32_t aAddr = smb + G1_AHI +
        (uint32_t)(wm * 16 + (sub & 1) * 8 + lrow) * ROWB + (sub >> 1) * 16;
    const uint32_t bAddr = smb + G1_BHI +
        (uint32_t)(wn * 64 + (sub >> 1) * 8 + lrow) * ROWB + (sub & 1) * 16;

    for (int kc = 0; kc < 8; kc++) {
        const int k0 = kc * 64;
#pragma unroll
        for (int t = tid; t < 1024; t += 256) {
            int r = t >> 4, c4 = t & 15;
            float4 v = *(const float4*)&x[(size_t)(bm + r) * INF_ + k0 + c4 * 4];
            __nv_bfloat16 h0 = __float2bfloat16(v.x), h1v = __float2bfloat16(v.y);
            __nv_bfloat16 h2 = __float2bfloat16(v.z), h3 = __float2bfloat16(v.w);
            __nv_bfloat16 l0 = __float2bfloat16(v.x - __bfloat162float(h0));
            __nv_bfloat16 l1 = __float2bfloat16(v.y - __bfloat162float(h1v));
            __nv_bfloat16 l2 = __float2bfloat16(v.z - __bfloat162float(h2));
            __nv_bfloat16 l3 = __float2bfloat16(v.w - __bfloat162float(h3));
            char* pa = sm + G1_AHI + r * ROWB + c4 * 8;
            *(__nv_bfloat162*)(pa)     = __nv_bfloat162(h0, h1v);
            *(__nv_bfloat162*)(pa + 4) = __nv_bfloat162(h2, h3);
            char* pl = sm + G1_ALO + r * ROWB + c4 * 8;
            *(__nv_bfloat162*)(pl)     = __nv_bfloat162(l0, l1);
            *(__nv_bfloat162*)(pl + 4) = __nv_bfloat162(l2, l3);
        }
#pragma unroll
        for (int t = tid; t < 1024; t += 256) {
            int r = t >> 3, cc = t & 7;
            *(uint4*)(sm + G1_BHI + r * ROWB + cc * 16) =
                *(const uint4*)(wh + (size_t)r * INF_ + k0 + cc * 8);
            *(uint4*)(sm + G1_BLO + r * ROWB + cc * 16) =
                *(const uint4*)(wl + (size_t)r * INF_ + k0 + cc * 8);
        }
        __syncthreads();

#pragma unroll
        for (int k = 0; k < 4; k++) {
            const int kb = k * 32;
            uint32_t ah[4], al[4];
            LDSM4(ah, aAddr + kb);
            LDSM4(al, aAddr + G1_ALO_OFF + kb);
#pragma unroll
            for (int pp = 0; pp < 4; pp++) {
                uint32_t bh[4], bl[4];
                LDSM4(bh, bAddr + pp * (16 * ROWB) + kb);
                LDSM4(bl, bAddr + pp * (16 * ROWB) + G1_BLO_OFF + kb);
                const int n0 = 2 * pp, n1 = 2 * pp + 1;
                mma_bf16(c[n0], ah, &bh[0]);
                mma_bf16(c[n1], ah, &bh[2]);
                mma_bf16(c[n0], ah, &bl[0]);
                mma_bf16(c[n1], ah, &bl[2]);
                mma_bf16(c[n0], al, &bh[0]);
                mma_bf16(c[n1], al, &bh[2]);
            }
        }
        __syncthreads();
    }

    const int r0 = bm + wm * 16 + g;
    const int col0 = wn * 64 + tg * 2;
    float ssA = 0.f, sdA = 0.f, ssB = 0.f, sdB = 0.f;
#pragma unroll
    for (int nt = 0; nt < 8; nt++) {
        *(float2*)&h1[(size_t)r0 * HF + col0 + nt * 8]       = make_float2(c[nt][0], c[nt][1]);
        *(float2*)&h1[(size_t)(r0 + 8) * HF + col0 + nt * 8] = make_float2(c[nt][2], c[nt][3]);
        float a0 = __ldg(&a_src[col0 + nt * 8]), a1 = __ldg(&a_src[col0 + nt * 8 + 1]);
        float d0 = __ldg(&a_dst[col0 + nt * 8]), d1 = __ldg(&a_dst[col0 + nt * 8 + 1]);
        ssA += c[nt][0] * a0 + c[nt][1] * a1;
        sdA += c[nt][0] * d0 + c[nt][1] * d1;
        ssB += c[nt][2] * a0 + c[nt][3] * a1;
        sdB += c[nt][2] * d0 + c[nt][3] * d1;
    }
#pragma unroll
    for (int o = 1; o <= 2; o <<= 1) {
        ssA += __shfl_xor_sync(0xffffffffu, ssA, o);
        sdA += __shfl_xor_sync(0xffffffffu, sdA, o);
        ssB += __shfl_xor_sync(0xffffffffu, ssB, o);
        sdB += __shfl_xor_sync(0xffffffffu, sdB, o);
    }
    const int rowA = wm * 16 + g, rowB = rowA + 8;
    if (tg == 0) {
        red[wn][0][rowA] = ssA; red[wn][0][rowB] = ssB;
        red[wn][1][rowA] = sdA; red[wn][1][rowB] = sdB;
    }
    __syncthreads();
    if (tid < 64) {
        os[bm + tid] = red[0][0][tid] + red[1][0][tid];
        od[bm + tid] = red[0][1][tid] + red[1][1][tid];
    }
}

// ============ A_pred = sigmoid(z z^T): ldmatrix + fused hi/lo mainloop =======
#define TILE_B (128 * ROWB)
#define ZT_AHI 0
#define ZT_ALO TILE_B
#define ZT_BHI (2 * TILE_B)
#define ZT_BLO (3 * TILE_B)
#define ZT_TOTAL (4 * TILE_B)       // 73728 B; mirror stage reuses it

__global__ __launch_bounds__(256, 2) void zzt_sym(const __nv_bfloat16* __restrict__ zh,
                                                  const __nv_bfloat16* __restrict__ zl,
                                                  float* __restrict__ out) {
    extern __shared__ char sm[];
    const uint32_t smb = (uint32_t)__cvta_generic_to_shared(sm);
    const int tid = threadIdx.x;

    int p = blockIdx.x;
    int bi = (int)((2.0f * NTILE + 1.0f -
                    sqrtf((2.0f * NTILE + 1.0f) * (2.0f * NTILE + 1.0f) - 8.0f * p)) * 0.5f);
    if (bi < 0) bi = 0;
    if (bi > NTILE - 1) bi = NTILE - 1;
    while (bi > 0 && bi * NTILE - bi * (bi - 1) / 2 > p) bi--;
    while ((bi + 1) * NTILE - (bi + 1) * bi / 2 <= p) bi++;
    const int bj = bi + (p - (bi * NTILE - bi * (bi - 1) / 2));
    const int bm = bi * 128, bn = bj * 128;

#pragma unroll
    for (int t = tid; t < 1024; t += 256) {
        int r = t >> 3, c = t & 7;
        *(uint4*)(sm + ZT_AHI + r * ROWB + c * 16) = *(const uint4*)(zh + (size_t)(bm + r) * 64 + c * 8);
        *(uint4*)(sm + ZT_ALO + r * ROWB + c * 16) = *(const uint4*)(zl + (size_t)(bm + r) * 64 + c * 8);
        *(uint4*)(sm + ZT_BHI + r * ROWB + c * 16) = *(const uint4*)(zh + (size_t)(bn + r) * 64 + c * 8);
        *(uint4*)(sm + ZT_BLO + r * ROWB + c * 16) = *(const uint4*)(zl + (size_t)(bn + r) * 64 + c * 8);
    }
    __syncthreads();

    const int wid = tid >> 5, lane = tid & 31;
    const int wm = wid & 3, wn = wid >> 2;
    const int sub = lane >> 3, lrow = lane & 7;

    const uint32_t aAddr0 = smb + ZT_AHI +
        (uint32_t)(wm * 32 + (sub & 1) * 8 + lrow) * ROWB + (sub >> 1) * 16;
    const uint32_t aAddr1 = aAddr0 + 16 * ROWB;
    const uint32_t bAddr = smb + ZT_BHI +
        (uint32_t)(wn * 64 + (sub >> 1) * 8 + lrow) * ROWB + (sub & 1) * 16;

    float c[2][8][4] = {};

#pragma unroll
    for (int k = 0; k < 4; k++) {
        const int kb = k * 32;
        uint32_t ah[2][4], al[2][4];
        LDSM4(ah[0], aAddr0 + kb);
        LDSM4(ah[1], aAddr1 + kb);
        LDSM4(al[0], aAddr0 + TILE_B + kb);
        LDSM4(al[1], aAddr1 + TILE_B + kb);
#pragma unroll
        for (int pp = 0; pp < 4; pp++) {
            uint32_t bh[4], bl[4];
            LDSM4(bh, bAddr + pp * (16 * ROWB) + kb);
            LDSM4(bl, bAddr + pp * (16 * ROWB) + TILE_B + kb);
            const int n0 = 2 * pp, n1 = 2 * pp + 1;
#pragma unroll
            for (int mt = 0; mt < 2; mt++) {
                mma_bf16(c[mt][n0], ah[mt], &bh[0]);
                mma_bf16(c[mt][n1], ah[mt], &bh[2]);
                mma_bf16(c[mt][n0], ah[mt], &bl[0]);
                mma_bf16(c[mt][n1], ah[mt], &bl[2]);
                mma_bf16(c[mt][n0], al[mt], &bh[0]);
                mma_bf16(c[mt][n1], al[mt], &bh[2]);
            }
        }
    }

    const bool mirror = (bi != bj);
    if (mirror) __syncthreads();     // only needed before reusing smem as stage
    float (*S)[129] = (float(*)[129])sm;
    const int g = lane >> 2, tg = lane & 3;

#pragma unroll
    for (int mt = 0; mt < 2; mt++) {
        const int r0 = wm * 32 + mt * 16 + g;
        const int c0 = wn * 64 + tg * 2;
#pragma unroll
        for (int nt = 0; nt < 8; nt++) {
            float s0 = 1.0f / (1.0f + __expf(-c[mt][nt][0]));
            float s1 = 1.0f / (1.0f + __expf(-c[mt][nt][1]));
            float s2 = 1.0f / (1.0f + __expf(-c[mt][nt][2]));
            float s3 = 1.0f / (1.0f + __expf(-c[mt][nt][3]));
            stg_cs_f2(&out[(size_t)(bm + r0) * NN + bn + c0 + nt * 8], s0, s1);
            stg_cs_f2(&out[(size_t)(bm + r0 + 8) * NN + bn + c0 + nt * 8], s2, s3);
            if (mirror) {
                S[r0][c0 + nt * 8]         = s0;
                S[r0][c0 + nt * 8 + 1]     = s1;
                S[r0 + 8][c0 + nt * 8]     = s2;
                S[r0 + 8][c0 + nt * 8 + 1] = s3;
            }
        }
    }
    if (mirror) {
        __syncthreads();
#pragma unroll 4
        for (int v = 0; v < 16; v++) {
            int idx = v * 256 + tid;
            int rr = idx >> 5, qc = (idx & 31) * 4;
            float4 o;
            o.x = S[qc + 0][rr];
            o.y = S[qc + 1][rr];
            o.z = S[qc + 2][rr];
            o.w = S[qc + 3][rr];
            stg_cs_f4(&out[(size_t)(bn + rr) * NN + bm + qc], o);
        }
    }
}

// ------ layer-2 GEMM (fp32 SIMT, 64x64 tiles) with fused alpha dots ----------
__global__ __launch_bounds__(256) void gemm2_a(const float* __restrict__ A,
                                               const float* __restrict__ B,
                                               const float* __restrict__ a_src,
                                               const float* __restrict__ a_dst,
                                               float* __restrict__ C,
                                               float* __restrict__ os,
                                               float* __restrict__ od) {
    __shared__ float As[16][64];
    __shared__ float Bs[16][64];
    const int tid = threadIdx.x;
    const int bm = blockIdx.x * 64;
    const int ty = tid >> 4, tx = tid & 15;
    float acc[4][4] = {};
    const int ra = tid >> 2, ka = (tid & 3) * 4;
    const int kb = tid >> 4, nb = (tid & 15) * 4;
    for (int k0 = 0; k0 < HF; k0 += 16) {
        float4 av = *(const float4*)&A[(size_t)(bm + ra) * HF + k0 + ka];
        float4 bv = *(const float4*)&B[(size_t)(k0 + kb) * OF + nb];
        As[ka + 0][ra] = av.x; As[ka + 1][ra] = av.y;
        As[ka + 2][ra] = av.z; As[ka + 3][ra] = av.w;
        *(float4*)&Bs[kb][nb] = bv;
        __syncthreads();
#pragma unroll
        for (int k = 0; k < 16; k++) {
            float4 a4 = *(const float4*)&As[k][ty * 4];
            float4 b4 = *(const float4*)&Bs[k][tx * 4];
            acc[0][0] += a4.x * b4.x; acc[0][1] += a4.x * b4.y;
            acc[0][2] += a4.x * b4.z; acc[0][3] += a4.x * b4.w;
            acc[1][0] += a4.y * b4.x; acc[1][1] += a4.y * b4.y;
            acc[1][2] += a4.y * b4.z; acc[1][3] += a4.y * b4.w;
            acc[2][0] += a4.z * b4.x; acc[2][1] += a4.z * b4.y;
            acc[2][2] += a4.z * b4.z; acc[2][3] += a4.z * b4.w;
            acc[3][0] += a4.w * b4.x; acc[3][1] += a4.w * b4.y;
            acc[3][2] += a4.w * b4.z; acc[3][3] += a4.w * b4.w;
        }
        __syncthreads();
    }
    float ss[4], sd[4];
#pragma unroll
    for (int i = 0; i < 4; i++) {
        float4 o = make_float4(acc[i][0], acc[i][1], acc[i][2], acc[i][3]);
        *(float4*)&C[(size_t)(bm + ty * 4 + i) * OF + tx * 4] = o;
        float a0 = __ldg(&a_src[tx * 4]),     d0 = __ldg(&a_dst[tx * 4]);
        float a1 = __ldg(&a_src[tx * 4 + 1]), d1 = __ldg(&a_dst[tx * 4 + 1]);
        float a2 = __ldg(&a_src[tx * 4 + 2]), d2 = __ldg(&a_dst[tx * 4 + 2]);
        float a3 = __ldg(&a_src[tx * 4 + 3]), d3 = __ldg(&a_dst[tx * 4 + 3]);
        ss[i] = acc[i][0] * a0 + acc[i][1] * a1 + acc[i][2] * a2 + acc[i][3] * a3;
        sd[i] = acc[i][0] * d0 + acc[i][1] * d1 + acc[i][2] * d2 + acc[i][3] * d3;
    }
#pragma unroll
    for (int o = 1; o <= 8; o <<= 1) {
#pragma unroll
        for (int i = 0; i < 4; i++) {
            ss[i] += __shfl_xor_sync(0xffffffffu, ss[i], o);
            sd[i] += __shfl_xor_sync(0xffffffffu, sd[i], o);
        }
    }
    if (tx == 0) {
#pragma unroll
        for (int i = 0; i < 4; i++) {
            os[bm + ty * 4 + i] = ss[i];
            od[bm + ty * 4 + i] = sd[i];
        }
    }
}

// ---------------- CSR build (1 edge/thread; self loops folded in scan) --------
__global__ void count_edges(const int* __restrict__ ei) {
    int i = blockIdx.x * blockDim.x + threadIdx.x;
    atomicAdd(&g_cnt[ei[EE + i]], 1);
}

// scan also re-zeroes g_cnt so the next graph replay needs no memset.
__global__ __launch_bounds__(1024) void scan_kernel() {
    __shared__ int sh[1024];
    int tid = threadIdx.x;
    int local[8];
    int s = 0;
#pragma unroll
    for (int j = 0; j < 8; j++) {
        int node = tid * 8 + j;
        local[j] = g_cnt[node] + 1;
        g_cnt[node] = 0;              // reset for next replay
        s += local[j];
    }
    sh[tid] = s;
    __syncthreads();
    for (int off = 1; off < 1024; off <<= 1) {
        int v = (tid >= off) ? sh[tid - off] : 0;
        __syncthreads();
        sh[tid] += v;
        __syncthreads();
    }
    int run = sh[tid] - s;  // exclusive prefix
#pragma unroll
    for (int j = 0; j < 8; j++) {
        int node = tid * 8 + j;
        g_off[node] = run;
        g_srcs[run] = node;   // self loop goes first
        g_fill[node] = 1;
        run += local[j];
    }
    if (tid == 1023) g_off[NN] = run;
}

__global__ void scatter_edges(const int* __restrict__ ei) {
    int i = blockIdx.x * blockDim.x + threadIdx.x;
    int src = ei[i], dst = ei[EE + i];
    int pos = g_off[dst] + atomicAdd(&g_fill[dst], 1);
    g_srcs[pos] = src;
}

// ------ GAT softmax-aggregate: float4 gather, group-per-edge -----------------
template <int F, bool DO_ELU, bool EMIT_HILO>
__global__ __launch_bounds__(128) void gat_aggregate(const float* __restrict__ h,
                                                     const float* __restrict__ as,
                                                     const float* __restrict__ adv,
                                                     const float* __restrict__ bias,
                                                     float* __restrict__ out,
                                                     __nv_bfloat16* __restrict__ zh,
                                                     __nv_bfloat16* __restrict__ zl) {
    constexpr int G  = F / 4;      // lanes per edge (32 or 16)
    constexpr int NG = 128 / G;    // edges in parallel (4 or 8)
    const int dst = blockIdx.x;
    const int tid = threadIdx.x;
    const int grp = tid / G, lane = tid % G;
    const int beg = g_off[dst], end = g_off[dst + 1];
    const float ad = adv[dst];
    __shared__ float  wbuf[128];
    __shared__ int    sbuf[128];
    __shared__ float4 red4[128];
    __shared__ float  sred[NG];

    float4 acc = make_float4(0.f, 0.f, 0.f, 0.f);
    float s = 0.f;
    for (int base = beg; base < end; base += 128) {
        int j = base + tid;
        if (j < end) {
            int sidx = g_srcs[j];
            float e = as[sidx] + ad;
            e = e > 0.f ? e : 0.2f * e;
            wbuf[tid] = __expf(e);
            sbuf[tid] = sidx;
        }
        __syncthreads();
        int cnt = min(128, end - base);
#pragma unroll 4
        for (int c = grp; c < cnt; c += NG) {
            float w = wbuf[c];
            float4 hv = *(const float4*)&h[(size_t)sbuf[c] * F + lane * 4];
            s += w;
            acc.x += w * hv.x; acc.y += w * hv.y;
            acc.z += w * hv.z; acc.w += w * hv.w;
        }
        __syncthreads();
    }
    red4[tid] = acc;
    if (lane == 0) sred[grp] = s;
    __syncthreads();
    if (tid < G) {
        float4 a = red4[tid];
        float st = sred[0];
#pragma unroll
        for (int gg = 1; gg < NG; gg++) {
            float4 b = red4[gg * G + tid];
            a.x += b.x; a.y += b.y; a.z += b.z; a.w += b.w;
            st += sred[gg];
        }
        float inv = __fdividef(1.0f, st);
        float4 bi = *(const float4*)&bias[tid * 4];
        float4 v;
        v.x = a.x * inv + bi.x;
        v.y = a.y * inv + bi.y;
        v.z = a.z * inv + bi.z;
        v.w = a.w * inv + bi.w;
        if (DO_ELU) {
            v.x = v.x > 0.f ? v.x : (__expf(v.x) - 1.0f);
            v.y = v.y > 0.f ? v.y : (__expf(v.y) - 1.0f);
            v.z = v.z > 0.f ? v.z : (__expf(v.z) - 1.0f);
            v.w = v.w > 0.f ? v.w : (__expf(v.w) - 1.0f);
        }
        *(float4*)&out[(size_t)dst * F + tid * 4] = v;
        if (EMIT_HILO) {
            __nv_bfloat16 h0 = __float2bfloat16(v.x), h1 = __float2bfloat16(v.y);
            __nv_bfloat16 h2 = __float2bfloat16(v.z), h3 = __float2bfloat16(v.w);
            __nv_bfloat16 l0 = __float2bfloat16(v.x - __bfloat162float(h0));
            __nv_bfloat16 l1 = __float2bfloat16(v.y - __bfloat162float(h1));
            __nv_bfloat16 l2 = __float2bfloat16(v.z - __bfloat162float(h2));
            __nv_bfloat16 l3 = __float2bfloat16(v.w - __bfloat162float(h3));
            *(__nv_bfloat162*)&zh[(size_t)dst * F + tid * 4]     = __nv_bfloat162(h0, h1);
            *(__nv_bfloat162*)&zh[(size_t)dst * F + tid * 4 + 2] = __nv_bfloat162(h2, h3);
            *(__nv_bfloat162*)&zl[(size_t)dst * F + tid * 4]     = __nv_bfloat162(l0, l1);
            *(__nv_bfloat162*)&zl[(size_t)dst * F + tid * 4 + 2] = __nv_bfloat162(l2, l3);
        }
    }
}

// ---------------- student-t soft assignment q ---------------------------------
__global__ __launch_bounds__(128) void q_kernel(const float* __restrict__ z,
                                                const float* __restrict__ centers,
                                                float* __restrict__ q) {
    __shared__ float c[KCL * OF];
    for (int i = threadIdx.x; i < KCL * OF; i += blockDim.x) c[i] = centers[i];
    __syncthreads();
    int node = blockIdx.x * blockDim.x + threadIdx.x;
    if (node >= NN) return;
    float zr[OF];
#pragma unroll
    for (int f = 0; f < OF; f++) zr[f] = z[(size_t)node * OF + f];
    float qs[KCL];
    float tot = 0.f;
#pragma unroll
    for (int k = 0; k < KCL; k++) {
        float d2 = 0.f;
#pragma unroll
        for (int f = 0; f < OF; f++) {
            float d = zr[f] - c[k * OF + f];
            d2 += d * d;
        }
        float qk = 1.0f / (1.0f + d2);
        qs[k] = qk;
        tot += qk;
    }
    float inv = 1.0f / tot;
#pragma unroll
    for (int k = 0; k < KCL; k += 4) {
        float4 o = make_float4(qs[k] * inv, qs[k + 1] * inv,
                               qs[k + 2] * inv, qs[k + 3] * inv);
        stg_cs_f4(&q[(size_t)node * KCL + k], o);
    }
}

// ---------------- launcher ----------------------------------------------------
extern "C" void kernel_launch(void* const* d_in, const int* in_sizes, int n_in,
                              void* d_out, int out_size) {
    const float* x      = (const float*)d_in[0];
    const int*   ei     = (const int*)d_in[1];
    const float* W1     = (const float*)d_in[2];
    const float* a_src1 = (const float*)d_in[3];
    const float* a_dst1 = (const float*)d_in[4];
    const float* b1     = (const float*)d_in[5];
    const float* W2     = (const float*)d_in[6];
    const float* a_src2 = (const float*)d_in[7];
    const float* a_dst2 = (const float*)d_in[8];
    const float* b2     = (const float*)d_in[9];
    const float* centers= (const float*)d_in[10];

    float* out    = (float*)d_out;
    float* z_out  = out;                         // [NN, OF]
    float* apred  = out + (size_t)NN * OF;       // [NN, NN]
    float* q_out  = apred + (size_t)NN * NN;     // [NN, KCL]

    float *h1, *x2, *h2, *as1, *ad1, *as2, *ad2;
    __nv_bfloat16 *zh, *zl, *wh, *wl;
    cudaGetSymbolAddress((void**)&h1,  g_h1);
    cudaGetSymbolAddress((void**)&x2,  g_x2);
    cudaGetSymbolAddress((void**)&h2,  g_h2);
    cudaGetSymbolAddress((void**)&as1, g_as1);
    cudaGetSymbolAddress((void**)&ad1, g_ad1);
    cudaGetSymbolAddress((void**)&as2, g_as2);
    cudaGetSymbolAddress((void**)&ad2, g_ad2);
    cudaGetSymbolAddress((void**)&zh,  g_zhi);
    cudaGetSymbolAddress((void**)&zl,  g_zlo);
    cudaGetSymbolAddress((void**)&wh,  g_w1thi);
    cudaGetSymbolAddress((void**)&wl,  g_w1tlo);

    cudaFuncSetAttribute(zzt_sym, cudaFuncAttributeMaxDynamicSharedMemorySize, ZT_TOTAL);
    cudaFuncSetAttribute(gemm1_fused, cudaFuncAttributeMaxDynamicSharedMemorySize, G1_TOTAL);

    static cudaStream_t s_side = nullptr;
    static cudaEvent_t ev_fork = nullptr, ev_csr = nullptr, ev_z = nullptr, ev_q = nullptr;
    if (s_side == nullptr) {
        cudaStreamCreateWithFlags(&s_side, cudaStreamNonBlocking);
        cudaEventCreateWithFlags(&ev_fork, cudaEventDisableTiming);
        cudaEventCreateWithFlags(&ev_csr,  cudaEventDisableTiming);
        cudaEventCreateWithFlags(&ev_z,    cudaEventDisableTiming);
        cudaEventCreateWithFlags(&ev_q,    cudaEventDisableTiming);
    }

    if (s_side != nullptr) {
        // ---- fork: CSR build on side stream, gemm1 path on main ----
        // (g_cnt is zero: module-load init on run 1, scan re-zeroes thereafter)
        cudaEventRecord(ev_fork, 0);
        cudaStreamWaitEvent(s_side, ev_fork, 0);
        count_edges<<<EE / 256, 256, 0, s_side>>>(ei);
        scan_kernel<<<1, 1024, 0, s_side>>>();
        scatter_edges<<<EE / 256, 256, 0, s_side>>>(ei);
        cudaEventRecord(ev_csr, s_side);

        cvt_w1t<<<64, 256>>>(W1, wh, wl);
        gemm1_fused<<<NN / 64, 256, G1_TOTAL>>>(x, wh, wl, a_src1, a_dst1, h1, as1, ad1);

        // ---- join: aggregate needs CSR + gemm1 ----
        cudaStreamWaitEvent(0, ev_csr, 0);
        gat_aggregate<HF, true, false><<<NN, 128>>>(h1, as1, ad1, b1, x2, nullptr, nullptr);

        gemm2_a<<<NN / 64, 256>>>(x2, W2, a_src2, a_dst2, h2, as2, ad2);
        gat_aggregate<OF, false, true><<<NN, 128>>>(h2, as2, ad2, b2, z_out, zh, zl);

        // ---- fork: q on side (needs z), zzt on main (needs zh/zl) ----
        cudaEventRecord(ev_z, 0);
        cudaStreamWaitEvent(s_side, ev_z, 0);
        q_kernel<<<NN / 128, 128, 0, s_side>>>(z_out, centers, q_out);
        cudaEventRecord(ev_q, s_side);

        zzt_sym<<<NPAIR, 256, ZT_TOTAL>>>(zh, zl, apred);
        cudaStreamWaitEvent(0, ev_q, 0);
    } else {
        // fallback: sequential on default stream
        count_edges<<<EE / 256, 256>>>(ei);
        scan_kernel<<<1, 1024>>>();
        scatter_edges<<<EE / 256, 256>>>(ei);
        cvt_w1t<<<64, 256>>>(W1, wh, wl);
        gemm1_fused<<<NN / 64, 256, G1_TOTAL>>>(x, wh, wl, a_src1, a_dst1, h1, as1, ad1);
        gat_aggregate<HF, true, false><<<NN, 128>>>(h1, as1, ad1, b1, x2, nullptr, nullptr);
        gemm2_a<<<NN / 64, 256>>>(x2, W2, a_src2, a_dst2, h2, as2, ad2);
        gat_aggregate<OF, false, true><<<NN, 128>>>(h2, as2, ad2, b2, z_out, zh, zl);
        zzt_sym<<<NPAIR, 256, ZT_TOTAL>>>(zh, zl, apred);
        q_kernel<<<NN / 128, 128>>>(z_out, centers, q_out);
    }
}